// round 9
// baseline (speedup 1.0000x reference)
#include <cuda_runtime.h>
#include <cuda_fp16.h>
#include <math.h>
#include <stdint.h>

#define BATCH   4
#define SEQLEN  4096
#define DIM     512
#define DINNER  1024
#define DSTATE  16
#define DCONV   4
#define M_TOK   (BATCH*SEQLEN)   // 16384

// ======================= PTX helpers (sm_80 baseline) ========================
__device__ __forceinline__ uint32_t smem_to_u32(const void* p) {
    uint32_t a;
    asm("{ .reg .u64 t; cvta.to.shared.u64 t, %1; cvt.u32.u64 %0, t; }"
        : "=r"(a) : "l"(p));
    return a;
}
#define CP_ASYNC16(saddr, gptr) \
    asm volatile("cp.async.cg.shared.global [%0], [%1], 16;" \
        :: "r"(saddr), "l"(gptr))
#define CP_COMMIT() asm volatile("cp.async.commit_group;" ::: "memory")
#define CP_WAIT1()  asm volatile("cp.async.wait_group 1;" ::: "memory")
#define CP_WAIT0()  asm volatile("cp.async.wait_group 0;" ::: "memory")

#define LDSM_X4(r, addr) \
    asm volatile("ldmatrix.sync.aligned.m8n8.x4.shared.b16 {%0,%1,%2,%3}, [%4];" \
        : "=r"((r)[0]), "=r"((r)[1]), "=r"((r)[2]), "=r"((r)[3]) : "r"(addr))

#define MMA_F16(d, a, b0, b1) \
    asm volatile("mma.sync.aligned.m16n8k16.row.col.f32.f16.f16.f32 " \
        "{%0,%1,%2,%3}, {%4,%5,%6,%7}, {%8,%9}, {%0,%1,%2,%3};" \
        : "+f"((d)[0]), "+f"((d)[1]), "+f"((d)[2]), "+f"((d)[3]) \
        : "r"((a)[0]), "r"((a)[1]), "r"((a)[2]), "r"((a)[3]), "r"(b0), "r"(b1))

// ======================= scratch =============================================
__device__ __align__(256) float g_xr  [(size_t)M_TOK * 2 * DINNER];
__device__ __align__(256) float g_xa  [(size_t)M_TOK * DINNER];
__device__ __align__(256) float g_wcat[2 * DSTATE * DINNER];
__device__ __align__(256) float g_dtb [(size_t)M_TOK * 2 * DSTATE];
__device__ __align__(256) float g_u   [M_TOK];
__device__ __align__(256) float g_adisc[(size_t)M_TOK * DSTATE];
__device__ __align__(256) float g_bu  [(size_t)M_TOK * DSTATE];
__device__ __align__(256) float g_y   [(size_t)M_TOK * DSTATE];
// fp16 GEMM operands
__device__ __align__(256) __half g_xh [(size_t)M_TOK * DIM];
__device__ __align__(256) __half g_yh [(size_t)M_TOK * DINNER];
__device__ __align__(256) __half g_wih[(size_t)2*DINNER * DIM];
__device__ __align__(256) __half g_woh[(size_t)DIM * DINNER];
// scan chunk summaries
#define SCHUNK  128
#define NCHUNK  (SEQLEN / SCHUNK)   // 32
__device__ float g_cA   [BATCH * DSTATE * NCHUNK];
__device__ float g_cV   [BATCH * DSTATE * NCHUNK];
__device__ float g_carry[BATCH * DSTATE * NCHUNK];

// ======================= HMMA fp16 GEMM ======================================
// C[M,N] = A[M,K] * B[N,K]^T, fp16 K-major inputs, fp32 out.
// Block tile 256x128, 512 threads (16 warps in 4x4, warp tile 64x32),
// K-chunk 64 halves (128B/row), cp.async double buffer, ldmatrix + mma.sync.
#define LG_ROWB   144
#define A_TILE_B  (256 * LG_ROWB)              // 36864 B
#define B_TILE_B  (128 * LG_ROWB)              // 18432 B
#define STAGE_B   (A_TILE_B + B_TILE_B)        // 55296 B
#define GH_SMEM   (2 * STAGE_B)                // 110592 B

__global__ __launch_bounds__(512, 1)
void gemm_hmma(const __half* __restrict__ A, const __half* __restrict__ B,
               float* __restrict__ C, int Nglob, int K)
{
    extern __shared__ char smem[];
    const uint32_t sb = smem_to_u32(smem);
    const int tid  = threadIdx.x;
    const int wid  = tid >> 5;
    const int lane = tid & 31;
    const int m0 = blockIdx.y * 256;
    const int n0 = blockIdx.x * 128;
    const int nch = K / 64;

    // warp -> 64(M) x 32(N) sub-tile; warps in 4(M) x 4(N) grid
    const int wm = (wid & 3) * 64;
    const int wn = (wid >> 2) * 32;

    float acc[4][4][4];
#pragma unroll
    for (int i = 0; i < 4; i++)
#pragma unroll
        for (int j = 0; j < 4; j++)
#pragma unroll
            for (int k = 0; k < 4; k++) acc[i][j][k] = 0.f;

    auto issue = [&](int c, int b) {
        const __half* Ag = A + (size_t)m0 * K + (size_t)c * 64;
        const __half* Bg = B + (size_t)n0 * K + (size_t)c * 64;
        const uint32_t sa  = sb + (uint32_t)(b * STAGE_B);
        const uint32_t sbm = sa + A_TILE_B;
        // A: 256 rows x 8 x 16B = 2048 ops -> 4 per thread
#pragma unroll
        for (int i = 0; i < 4; i++) {
            int idx = tid + i * 512;
            int row = idx >> 3, cc = idx & 7;
            CP_ASYNC16(sa + (uint32_t)(row * LG_ROWB + cc * 16),
                       Ag + (size_t)row * K + cc * 8);
        }
        // B: 128 rows x 8 = 1024 ops -> 2 per thread
#pragma unroll
        for (int i = 0; i < 2; i++) {
            int idx = tid + i * 512;
            int row = idx >> 3, cc = idx & 7;
            CP_ASYNC16(sbm + (uint32_t)(row * LG_ROWB + cc * 16),
                       Bg + (size_t)row * K + cc * 8);
        }
        CP_COMMIT();
    };

    issue(0, 0);
    for (int c = 0; c < nch; c++) {
        const int buf = c & 1;
        if (c + 1 < nch) { issue(c + 1, buf ^ 1); CP_WAIT1(); }
        else             { CP_WAIT0(); }
        __syncthreads();

        const uint32_t aBase = sb + (uint32_t)(buf * STAGE_B);
        const uint32_t bBase = aBase + A_TILE_B;
        const int lrow = lane & 15;
        const int lcol = (lane >> 4) * 16;
#pragma unroll
        for (int ks = 0; ks < 4; ks++) {
            uint32_t af[4][4], bfr[2][4];
#pragma unroll
            for (int mt = 0; mt < 4; mt++)
                LDSM_X4(af[mt], aBase + (uint32_t)((wm + mt*16 + lrow) * LG_ROWB + ks*32 + lcol));
#pragma unroll
            for (int ng = 0; ng < 2; ng++)
                LDSM_X4(bfr[ng], bBase + (uint32_t)((wn + ng*16 + lrow) * LG_ROWB + ks*32 + lcol));
#pragma unroll
            for (int mt = 0; mt < 4; mt++)
#pragma unroll
                for (int nt = 0; nt < 4; nt++) {
                    const int ng = nt >> 1, hi = nt & 1;
                    MMA_F16(acc[mt][nt], af[mt], bfr[ng][hi], bfr[ng][2 + hi]);
                }
        }
        __syncthreads();
    }

    const int er = lane >> 2;
    const int ec = (lane & 3) * 2;
#pragma unroll
    for (int mt = 0; mt < 4; mt++) {
        const int rbase = m0 + wm + mt * 16;
#pragma unroll
        for (int nt = 0; nt < 4; nt++) {
            const int col = n0 + wn + nt * 8 + ec;
            *reinterpret_cast<float2*>(C + (size_t)(rbase + er)     * Nglob + col) =
                make_float2(acc[mt][nt][0], acc[mt][nt][1]);
            *reinterpret_cast<float2*>(C + (size_t)(rbase + er + 8) * Nglob + col) =
                make_float2(acc[mt][nt][2], acc[mt][nt][3]);
        }
    }
}

// ======================= fp32 -> fp16 conversion ==============================
__global__ void tohalf_kernel(const float* __restrict__ src, __half* __restrict__ dst)
{
    long i = ((long)blockIdx.x * blockDim.x + threadIdx.x) * 4;
    float4 v = *reinterpret_cast<const float4*>(src + i);
    *reinterpret_cast<__half2*>(dst + i)     = __floats2half2_rn(v.x, v.y);
    *reinterpret_cast<__half2*>(dst + i + 2) = __floats2half2_rn(v.z, v.w);
}

// ======================= SIMT NT GEMM (small dt/B_proj only) =================
template<int BM, int BN, int BK, int TM, int TN>
__global__ __launch_bounds__((BM/TM)*(BN/TN))
void gemm_nt(const float* __restrict__ A, const float* __restrict__ B,
             float* __restrict__ C, int M, int N, int K)
{
    constexpr int TX = BN / TN;
    constexpr int TY = BM / TM;
    constexpr int NT = TX * TY;
    __shared__ float As[BK][BM];
    __shared__ float Bs[BK][BN];
    const int tid = threadIdx.x;
    const int tx = tid % TX, ty = tid / TX;
    const int m0 = blockIdx.y * BM, n0 = blockIdx.x * BN;
    float acc[TM][TN];
#pragma unroll
    for (int i = 0; i < TM; i++)
#pragma unroll
        for (int j = 0; j < TN; j++) acc[i][j] = 0.f;
    for (int k0 = 0; k0 < K; k0 += BK) {
#pragma unroll
        for (int i = tid; i < BM*BK/4; i += NT) {
            int r = i / (BK/4), c4 = i % (BK/4);
            float4 v = *reinterpret_cast<const float4*>(&A[(size_t)(m0+r)*K + k0 + c4*4]);
            As[c4*4+0][r]=v.x; As[c4*4+1][r]=v.y; As[c4*4+2][r]=v.z; As[c4*4+3][r]=v.w;
        }
#pragma unroll
        for (int i = tid; i < BN*BK/4; i += NT) {
            int r = i / (BK/4), c4 = i % (BK/4);
            float4 v = *reinterpret_cast<const float4*>(&B[(size_t)(n0+r)*K + k0 + c4*4]);
            Bs[c4*4+0][r]=v.x; Bs[c4*4+1][r]=v.y; Bs[c4*4+2][r]=v.z; Bs[c4*4+3][r]=v.w;
        }
        __syncthreads();
#pragma unroll
        for (int k = 0; k < BK; k++) {
            float ar[TM], br[TN];
#pragma unroll
            for (int i = 0; i < TM; i++) ar[i] = As[k][ty*TM+i];
#pragma unroll
            for (int j = 0; j < TN; j++) br[j] = Bs[k][tx*TN+j];
#pragma unroll
            for (int i = 0; i < TM; i++)
#pragma unroll
                for (int j = 0; j < TN; j++) acc[i][j] = fmaf(ar[i], br[j], acc[i][j]);
        }
        __syncthreads();
    }
#pragma unroll
    for (int i = 0; i < TM; i++) {
        float* crow = &C[(size_t)(m0+ty*TM+i)*N + n0 + tx*TN];
#pragma unroll
        for (int j = 0; j < TN; j++) crow[j] = acc[i][j];
    }
}

// ======================= pointwise / aux kernels =============================
__global__ void wcat_kernel(const float* __restrict__ Wx, const float* __restrict__ Wdt)
{
    int idx = blockIdx.x * blockDim.x + threadIdx.x;
    int row = idx >> 10;
    g_wcat[idx] = (row < DSTATE) ? Wdt[idx] : Wx[idx];
}

__global__ void conv_silu_kernel(const float* __restrict__ cw, const float* __restrict__ cb)
{
    int idx = blockIdx.x * blockDim.x + threadIdx.x;
    int c4 = idx & (DINNER/4 - 1);
    int m  = idx >> 8;
    int c  = c4 * 4;
    int l  = m & (SEQLEN - 1);
    float w[4][4];
#pragma unroll
    for (int j = 0; j < 4; j++)
        *reinterpret_cast<float4*>(w[j]) =
            *reinterpret_cast<const float4*>(cw + (size_t)(c + j) * DCONV);
    float4 b = *reinterpret_cast<const float4*>(cb + c);
    float a0 = b.x, a1 = b.y, a2 = b.z, a3 = b.w;
#pragma unroll
    for (int t = 0; t < DCONV; t++) {
        int ls = l - (DCONV - 1) + t;
        if (ls >= 0) {
            float4 xv = *reinterpret_cast<const float4*>(
                g_xr + (size_t)(m - (DCONV - 1) + t) * (2 * DINNER) + c);
            a0 = fmaf(w[0][t], xv.x, a0);
            a1 = fmaf(w[1][t], xv.y, a1);
            a2 = fmaf(w[2][t], xv.z, a2);
            a3 = fmaf(w[3][t], xv.w, a3);
        }
    }
    float4 o;
    o.x = a0 / (1.f + expf(-a0));
    o.y = a1 / (1.f + expf(-a1));
    o.z = a2 / (1.f + expf(-a2));
    o.w = a3 / (1.f + expf(-a3));
    *reinterpret_cast<float4*>(g_xa + (size_t)m * DINNER + c) = o;
}

__global__ void u_kernel()
{
    int gw = (blockIdx.x * blockDim.x + threadIdx.x) >> 5;
    int lane = threadIdx.x & 31;
    if (gw >= M_TOK) return;
    const float* xa = g_xa + (size_t)gw * DINNER;
    float v = xa[lane] + xa[lane + 32];
#pragma unroll
    for (int o = 16; o; o >>= 1) v += __shfl_down_sync(0xffffffffu, v, o);
    if (lane == 0) g_u[gw] = v * (1.f / 64.f);
}

__global__ void dtbu_kernel(const float* __restrict__ bdt, const float* __restrict__ Alog)
{
    int idx = blockIdx.x * blockDim.x + threadIdx.x;
    int m = idx >> 4;
    int n = idx & (DSTATE - 1);
    float raw = g_dtb[(size_t)m * 2 * DSTATE + n] + bdt[n];
    float dt  = raw > 20.f ? raw : log1pf(expf(raw));
    float bp  = g_dtb[(size_t)m * 2 * DSTATE + DSTATE + n];
    float A   = -expf(Alog[n]);
    g_adisc[idx] = expf(A * dt);
    g_bu[idx]    = dt * bp * g_u[m];
}

// -------- chunked scan (3 passes) --------
__global__ void scan_part_kernel()
{
    int t = blockIdx.x * blockDim.x + threadIdx.x;
    int chain = t >> 5, c = t & 31;
    int b = chain >> 4, n = chain & 15;
    size_t base = ((size_t)(b * SEQLEN + c * SCHUNK)) * DSTATE + n;
    float A = 1.f, V = 0.f;
#pragma unroll 8
    for (int i = 0; i < SCHUNK; i++) {
        float a = g_adisc[base + (size_t)i * DSTATE];
        float v = g_bu   [base + (size_t)i * DSTATE];
        V = fmaf(a, V, v);
        A *= a;
    }
    g_cA[chain * NCHUNK + c] = A;
    g_cV[chain * NCHUNK + c] = V;
}
__global__ void scan_mid_kernel()
{
    int chain = threadIdx.x;
    float s = 0.f;
#pragma unroll
    for (int c = 0; c < NCHUNK; c++) {
        g_carry[chain * NCHUNK + c] = s;
        s = fmaf(g_cA[chain * NCHUNK + c], s, g_cV[chain * NCHUNK + c]);
    }
}
__global__ void scan_apply_kernel()
{
    int t = blockIdx.x * blockDim.x + threadIdx.x;
    int chain = t >> 5, c = t & 31;
    int b = chain >> 4, n = chain & 15;
    size_t base = ((size_t)(b * SEQLEN + c * SCHUNK)) * DSTATE + n;
    float s = g_carry[chain * NCHUNK + c];
#pragma unroll 8
    for (int i = 0; i < SCHUNK; i++) {
        float a = g_adisc[base + (size_t)i * DSTATE];
        float v = g_bu   [base + (size_t)i * DSTATE];
        s = fmaf(a, s, v);
        g_y[base + (size_t)i * DSTATE] = s;
    }
}

// -------- gate + skip, fp16 output for GEMM2 ---------------------------------
__global__ void elt_kernel(const float* __restrict__ Dp)
{
    int idx = blockIdx.x * blockDim.x + threadIdx.x;
    int c4 = idx & (DINNER/4 - 1);
    int m  = idx >> 8;
    int c  = c4 * 4;
    float yv  = g_y[(size_t)m * DSTATE + (c >> 6)];
    float4 xa = *reinterpret_cast<const float4*>(g_xa + (size_t)m * DINNER + c);
    float4 D  = *reinterpret_cast<const float4*>(Dp + c);
    float4 r  = *reinterpret_cast<const float4*>(g_xr + (size_t)m * 2 * DINNER + DINNER + c);
    float4 o;
    o.x = (yv + xa.x * D.x) * (r.x / (1.f + expf(-r.x)));
    o.y = (yv + xa.y * D.y) * (r.y / (1.f + expf(-r.y)));
    o.z = (yv + xa.z * D.z) * (r.z / (1.f + expf(-r.z)));
    o.w = (yv + xa.w * D.w) * (r.w / (1.f + expf(-r.w)));

    __half* row = g_yh + (size_t)m * DINNER;
    *reinterpret_cast<__half2*>(row + c)     = __floats2half2_rn(o.x, o.y);
    *reinterpret_cast<__half2*>(row + c + 2) = __floats2half2_rn(o.z, o.w);
}

// ======================= launch ==============================================
extern "C" void kernel_launch(void* const* d_in, const int* in_sizes, int n_in,
                              void* d_out, int out_size)
{
    const float* x      = (const float*)d_in[0];
    const float* W_in   = (const float*)d_in[1];
    const float* conv_w = (const float*)d_in[2];
    const float* conv_b = (const float*)d_in[3];
    const float* W_x    = (const float*)d_in[4];
    const float* W_dt   = (const float*)d_in[5];
    const float* b_dt   = (const float*)d_in[6];
    const float* A_log  = (const float*)d_in[7];
    const float* D_par  = (const float*)d_in[8];
    const float* W_out  = (const float*)d_in[9];
    float* out = (float*)d_out;

    float* xr;   cudaGetSymbolAddress((void**)&xr,   g_xr);
    float* xa;   cudaGetSymbolAddress((void**)&xa,   g_xa);
    float* wcat; cudaGetSymbolAddress((void**)&wcat, g_wcat);
    float* dtb;  cudaGetSymbolAddress((void**)&dtb,  g_dtb);
    __half* xh;  cudaGetSymbolAddress((void**)&xh,  g_xh);
    __half* yh;  cudaGetSymbolAddress((void**)&yh,  g_yh);
    __half* wih; cudaGetSymbolAddress((void**)&wih, g_wih);
    __half* woh; cudaGetSymbolAddress((void**)&woh, g_woh);

    cudaFuncSetAttribute(gemm_hmma, cudaFuncAttributeMaxDynamicSharedMemorySize, GH_SMEM);

    // weight / input conversion to fp16
    wcat_kernel<<<(2*DSTATE*DINNER)/256, 256>>>(W_x, W_dt);
    tohalf_kernel<<<(2*DINNER*DIM)/1024, 256>>>(W_in, wih);
    tohalf_kernel<<<(DIM*DINNER)/1024, 256>>>(W_out, woh);
    tohalf_kernel<<<((long)M_TOK*DIM)/1024, 256>>>(x, xh);

    // GEMM1: xr = x @ W_in^T   [16384 x 2048 x 512] fp16 HMMA
    gemm_hmma<<<dim3(2*DINNER/128, M_TOK/256), 512, GH_SMEM>>>(
        xh, wih, xr, 2*DINNER, DIM);

    conv_silu_kernel<<<(M_TOK*(DINNER/4))/256, 256>>>(conv_w, conv_b);
    u_kernel<<<(M_TOK*32)/256, 256>>>();

    // small GEMM: [16384 x 32 x 1024] fp32 SIMT
    gemm_nt<64,32,16,4,2><<<dim3(1, M_TOK/64), 256>>>(xa, wcat, dtb, M_TOK, 2*DSTATE, DINNER);

    dtbu_kernel<<<(M_TOK*DSTATE)/256, 256>>>(b_dt, A_log);

    scan_part_kernel<<<(BATCH*DSTATE*NCHUNK)/256, 256>>>();
    scan_mid_kernel<<<1, BATCH*DSTATE>>>();
    scan_apply_kernel<<<(BATCH*DSTATE*NCHUNK)/256, 256>>>();

    elt_kernel<<<(M_TOK*(DINNER/4))/256, 256>>>(D_par);

    // GEMM2: out = y_full @ W_out^T  [16384 x 512 x 1024] fp16 HMMA
    gemm_hmma<<<dim3(DIM/128, M_TOK/256), 512, GH_SMEM>>>(
        yh, woh, out, DIM, DINNER);
}

// round 10
// speedup vs baseline: 1.1533x; 1.1533x over previous
#include <cuda_runtime.h>
#include <cuda_fp16.h>
#include <math.h>
#include <stdint.h>

#define BATCH   4
#define SEQLEN  4096
#define DIM     512
#define DINNER  1024
#define DSTATE  16
#define DCONV   4
#define M_TOK   (BATCH*SEQLEN)   // 16384

// ======================= PTX helpers (sm_80 baseline) ========================
__device__ __forceinline__ uint32_t smem_to_u32(const void* p) {
    uint32_t a;
    asm("{ .reg .u64 t; cvta.to.shared.u64 t, %1; cvt.u32.u64 %0, t; }"
        : "=r"(a) : "l"(p));
    return a;
}
#define CP_ASYNC16(saddr, gptr) \
    asm volatile("cp.async.cg.shared.global [%0], [%1], 16;" \
        :: "r"(saddr), "l"(gptr))
#define CP_COMMIT() asm volatile("cp.async.commit_group;" ::: "memory")
#define CP_WAIT1()  asm volatile("cp.async.wait_group 1;" ::: "memory")
#define CP_WAIT0()  asm volatile("cp.async.wait_group 0;" ::: "memory")

#define LDSM_X4(r, addr) \
    asm volatile("ldmatrix.sync.aligned.m8n8.x4.shared.b16 {%0,%1,%2,%3}, [%4];" \
        : "=r"((r)[0]), "=r"((r)[1]), "=r"((r)[2]), "=r"((r)[3]) : "r"(addr))

#define MMA_F16(d, a, b0, b1) \
    asm volatile("mma.sync.aligned.m16n8k16.row.col.f32.f16.f16.f32 " \
        "{%0,%1,%2,%3}, {%4,%5,%6,%7}, {%8,%9}, {%0,%1,%2,%3};" \
        : "+f"((d)[0]), "+f"((d)[1]), "+f"((d)[2]), "+f"((d)[3]) \
        : "r"((a)[0]), "r"((a)[1]), "r"((a)[2]), "r"((a)[3]), "r"(b0), "r"(b1))

// ======================= scratch =============================================
__device__ __align__(256) float  g_xa  [(size_t)M_TOK * DINNER];    // fp32 xa
__device__ __align__(256) float  g_dtb [(size_t)M_TOK * 2 * DSTATE];
__device__ __align__(256) float  g_u   [M_TOK];
__device__ __align__(256) float  g_adisc[(size_t)M_TOK * DSTATE];
__device__ __align__(256) float  g_bu  [(size_t)M_TOK * DSTATE];
__device__ __align__(256) float  g_y   [(size_t)M_TOK * DSTATE];
// fp16 planes
__device__ __align__(256) __half g_xh  [(size_t)M_TOK * DIM];       // x
__device__ __align__(256) __half g_xih [(size_t)M_TOK * DINNER];    // xi (GEMM1 out)
__device__ __align__(256) __half g_resh[(size_t)M_TOK * DINNER];    // silu(res)
__device__ __align__(256) __half g_xah [(size_t)M_TOK * DINNER];    // xa fp16
__device__ __align__(256) __half g_yh  [(size_t)M_TOK * DINNER];    // y_full
__device__ __align__(256) __half g_wih [(size_t)2*DINNER * DIM];
__device__ __align__(256) __half g_woh [(size_t)DIM * DINNER];
__device__ __align__(256) __half g_wch [2 * DSTATE * DINNER];       // [W_dt;W_x lo] fp16
// scan chunk summaries
#define SCHUNK  128
#define NCHUNK  (SEQLEN / SCHUNK)   // 32
__device__ float g_cA   [BATCH * DSTATE * NCHUNK];
__device__ float g_cV   [BATCH * DSTATE * NCHUNK];
__device__ float g_carry[BATCH * DSTATE * NCHUNK];

// ======================= HMMA fp16 GEMM (R7 config) ==========================
// C = A[M,K] * B[N,K]^T. Block tile 128x128, 256 threads (8 warps 4x2,
// warp tile 32x64), K-chunk 64, cp.async double buffer.
// MODE 0: fp32 C (Nglob stride). MODE 1: GEMM1 split epilogue -> g_xih/g_resh.
#define LG_ROWB   144
#define LG_TILE_B (128 * LG_ROWB)          // 18432 B
#define GH_SMEM   (4 * LG_TILE_B)          // 73728 B

template<int MODE>
__global__ __launch_bounds__(256, 2)
void gemm_hmma(const __half* __restrict__ A, const __half* __restrict__ B,
               float* __restrict__ C, int Nglob, int K)
{
    extern __shared__ char smem[];
    const uint32_t sb = smem_to_u32(smem);
    const int tid  = threadIdx.x;
    const int wid  = tid >> 5;
    const int lane = tid & 31;
    const int m0 = blockIdx.y * 128;
    const int n0 = blockIdx.x * 128;
    const int nch = K / 64;

    const int wm = (wid & 3) * 32;
    const int wn = (wid >> 2) * 64;
    const uint32_t offA[2] = { 0u,              2u * LG_TILE_B };
    const uint32_t offB[2] = { (uint32_t)LG_TILE_B, 3u * LG_TILE_B };

    float acc[2][8][4];
#pragma unroll
    for (int i = 0; i < 2; i++)
#pragma unroll
        for (int j = 0; j < 8; j++)
#pragma unroll
            for (int k = 0; k < 4; k++) acc[i][j][k] = 0.f;

    auto issue = [&](int c, int b) {
        const __half* Ag = A + (size_t)m0 * K + (size_t)c * 64;
        const __half* Bg = B + (size_t)n0 * K + (size_t)c * 64;
        const uint32_t sa  = sb + offA[b];
        const uint32_t sbm = sb + offB[b];
#pragma unroll
        for (int i = 0; i < 4; i++) {
            int idx = tid + i * 256;
            int row = idx >> 3, cc = idx & 7;
            CP_ASYNC16(sa  + (uint32_t)(row * LG_ROWB + cc * 16),
                       Ag + (size_t)row * K + cc * 8);
            CP_ASYNC16(sbm + (uint32_t)(row * LG_ROWB + cc * 16),
                       Bg + (size_t)row * K + cc * 8);
        }
        CP_COMMIT();
    };

    issue(0, 0);
    for (int c = 0; c < nch; c++) {
        const int buf = c & 1;
        if (c + 1 < nch) { issue(c + 1, buf ^ 1); CP_WAIT1(); }
        else             { CP_WAIT0(); }
        __syncthreads();

        const uint32_t aBase = sb + offA[buf];
        const uint32_t bBase = sb + offB[buf];
        const int lrow = lane & 15;
        const int lcol = (lane >> 4) * 16;
#pragma unroll
        for (int ks = 0; ks < 4; ks++) {
            uint32_t af[2][4], bfr[4][4];
#pragma unroll
            for (int mt = 0; mt < 2; mt++)
                LDSM_X4(af[mt], aBase + (uint32_t)((wm + mt*16 + lrow) * LG_ROWB + ks*32 + lcol));
#pragma unroll
            for (int ng = 0; ng < 4; ng++)
                LDSM_X4(bfr[ng], bBase + (uint32_t)((wn + ng*16 + lrow) * LG_ROWB + ks*32 + lcol));
#pragma unroll
            for (int mt = 0; mt < 2; mt++)
#pragma unroll
                for (int nt = 0; nt < 8; nt++) {
                    const int ng = nt >> 1, hi = nt & 1;
                    MMA_F16(acc[mt][nt], af[mt], bfr[ng][hi], bfr[ng][2 + hi]);
                }
        }
        __syncthreads();
    }

    const int er = lane >> 2;
    const int ec = (lane & 3) * 2;
    if (MODE == 0) {
#pragma unroll
        for (int mt = 0; mt < 2; mt++) {
            const int rbase = m0 + wm + mt * 16;
#pragma unroll
            for (int nt = 0; nt < 8; nt++) {
                const int col = n0 + wn + nt * 8 + ec;
                *reinterpret_cast<float2*>(C + (size_t)(rbase + er)     * Nglob + col) =
                    make_float2(acc[mt][nt][0], acc[mt][nt][1]);
                *reinterpret_cast<float2*>(C + (size_t)(rbase + er + 8) * Nglob + col) =
                    make_float2(acc[mt][nt][2], acc[mt][nt][3]);
            }
        }
    } else {
        // GEMM1: cols < DINNER -> xi (fp16); cols >= DINNER -> silu(res) fp16.
        const bool isRes = (n0 >= DINNER);   // uniform per CTA (n0 mult of 128)
#pragma unroll
        for (int mt = 0; mt < 2; mt++) {
            const int rbase = m0 + wm + mt * 16;
#pragma unroll
            for (int nt = 0; nt < 8; nt++) {
                int col = n0 + wn + nt * 8 + ec;
                float v0 = acc[mt][nt][0], v1 = acc[mt][nt][1];
                float v2 = acc[mt][nt][2], v3 = acc[mt][nt][3];
                if (isRes) {
                    col -= DINNER;
                    v0 = v0 / (1.f + expf(-v0));
                    v1 = v1 / (1.f + expf(-v1));
                    v2 = v2 / (1.f + expf(-v2));
                    v3 = v3 / (1.f + expf(-v3));
                    __half* dst = g_resh;
                    *reinterpret_cast<__half2*>(dst + (size_t)(rbase + er)     * DINNER + col) =
                        __floats2half2_rn(v0, v1);
                    *reinterpret_cast<__half2*>(dst + (size_t)(rbase + er + 8) * DINNER + col) =
                        __floats2half2_rn(v2, v3);
                } else {
                    __half* dst = g_xih;
                    *reinterpret_cast<__half2*>(dst + (size_t)(rbase + er)     * DINNER + col) =
                        __floats2half2_rn(v0, v1);
                    *reinterpret_cast<__half2*>(dst + (size_t)(rbase + er + 8) * DINNER + col) =
                        __floats2half2_rn(v2, v3);
                }
            }
        }
    }
}

// ======================= small HMMA GEMM: dtb = xa_h @ wcat_h^T ==============
// M=16384, N=32, K=1024. Block 128(M)x32(N), 256 thr (8 warps, warp 16x32).
// B (32x1024 fp16) loaded fully into smem once; A double-buffered 64-chunks.
#define SB_ROWB   2064                        // 1024 halves + 8 pad
#define SB_BYTES  (32 * SB_ROWB)              // 66048
#define SA_TILE   (128 * LG_ROWB)             // 18432
#define GS_SMEM   (SB_BYTES + 2 * SA_TILE)    // 102912

__global__ __launch_bounds__(256, 1)
void gemm_small(const __half* __restrict__ A, const __half* __restrict__ B,
                float* __restrict__ C)
{
    extern __shared__ char smem[];
    const uint32_t sb = smem_to_u32(smem);
    const int tid  = threadIdx.x;
    const int wid  = tid >> 5;
    const int lane = tid & 31;
    const int m0 = blockIdx.x * 128;
    const int K = DINNER;
    const int nch = K / 64;                   // 16

    // load full B (32 rows x 2048B)
    {
#pragma unroll
        for (int i = 0; i < 16; i++) {
            int idx = tid + i * 256;          // 0..4095
            int row = idx >> 7, cc = idx & 127;
            CP_ASYNC16(sb + (uint32_t)(row * SB_ROWB + cc * 16),
                       B + (size_t)row * K + cc * 8);
        }
        CP_COMMIT();
    }
    const uint32_t offA[2] = { (uint32_t)SB_BYTES, (uint32_t)(SB_BYTES + SA_TILE) };

    auto issueA = [&](int c, int b) {
        const __half* Ag = A + (size_t)m0 * K + (size_t)c * 64;
        const uint32_t sa = sb + offA[b];
#pragma unroll
        for (int i = 0; i < 4; i++) {
            int idx = tid + i * 256;          // 0..1023
            int row = idx >> 3, cc = idx & 7;
            CP_ASYNC16(sa + (uint32_t)(row * LG_ROWB + cc * 16),
                       Ag + (size_t)row * K + cc * 8);
        }
        CP_COMMIT();
    };

    const int wm = wid * 16;                  // warp tile 16(M) x 32(N)
    float acc[4][4];
#pragma unroll
    for (int j = 0; j < 4; j++)
#pragma unroll
        for (int k = 0; k < 4; k++) acc[j][k] = 0.f;

    issueA(0, 0);
    for (int c = 0; c < nch; c++) {
        const int buf = c & 1;
        if (c + 1 < nch) { issueA(c + 1, buf ^ 1); CP_WAIT1(); }
        else             { CP_WAIT0(); }
        __syncthreads();

        const uint32_t aBase = sb + offA[buf];
        const int lrow = lane & 15;
        const int lcol = (lane >> 4) * 16;
#pragma unroll
        for (int ks = 0; ks < 4; ks++) {
            uint32_t af[4], bfr[2][4];
            LDSM_X4(af, aBase + (uint32_t)((wm + lrow) * LG_ROWB + ks*32 + lcol));
#pragma unroll
            for (int ng = 0; ng < 2; ng++)
                LDSM_X4(bfr[ng], sb + (uint32_t)((ng*16 + lrow) * SB_ROWB + (c*4 + ks)*32 + lcol));
#pragma unroll
            for (int nt = 0; nt < 4; nt++) {
                const int ng = nt >> 1, hi = nt & 1;
                MMA_F16(acc[nt], af, bfr[ng][hi], bfr[ng][2 + hi]);
            }
        }
        __syncthreads();
    }

    const int er = lane >> 2;
    const int ec = (lane & 3) * 2;
#pragma unroll
    for (int nt = 0; nt < 4; nt++) {
        const int col = nt * 8 + ec;
        *reinterpret_cast<float2*>(C + (size_t)(m0 + wm + er)     * 32 + col) =
            make_float2(acc[nt][0], acc[nt][1]);
        *reinterpret_cast<float2*>(C + (size_t)(m0 + wm + er + 8) * 32 + col) =
            make_float2(acc[nt][2], acc[nt][3]);
    }
}

// ======================= conversions / pointwise =============================
__global__ void tohalf_kernel(const float* __restrict__ src, __half* __restrict__ dst)
{
    long i = ((long)blockIdx.x * blockDim.x + threadIdx.x) * 4;
    float4 v = *reinterpret_cast<const float4*>(src + i);
    *reinterpret_cast<__half2*>(dst + i)     = __floats2half2_rn(v.x, v.y);
    *reinterpret_cast<__half2*>(dst + i + 2) = __floats2half2_rn(v.z, v.w);
}

// wcat fp16: rows 0..15 = W_dt, 16..31 = W_x rows 16..31
__global__ void wcat_kernel(const float* __restrict__ Wx, const float* __restrict__ Wdt)
{
    int idx = blockIdx.x * blockDim.x + threadIdx.x;   // 32*1024
    int row = idx >> 10;
    float v = (row < DSTATE) ? Wdt[idx] : Wx[idx];
    g_wch[idx] = __float2half_rn(v);
}

// depthwise conv(4)+bias+SiLU, fp16 in, fp32 + fp16 out
__global__ void conv_silu_kernel(const float* __restrict__ cw, const float* __restrict__ cb)
{
    int idx = blockIdx.x * blockDim.x + threadIdx.x;   // M_TOK * DINNER/4
    int c4 = idx & (DINNER/4 - 1);
    int m  = idx >> 8;
    int c  = c4 * 4;
    int l  = m & (SEQLEN - 1);
    float w[4][4];
#pragma unroll
    for (int j = 0; j < 4; j++)
        *reinterpret_cast<float4*>(w[j]) =
            *reinterpret_cast<const float4*>(cw + (size_t)(c + j) * DCONV);
    float4 b = *reinterpret_cast<const float4*>(cb + c);
    float a0 = b.x, a1 = b.y, a2 = b.z, a3 = b.w;
#pragma unroll
    for (int t = 0; t < DCONV; t++) {
        int ls = l - (DCONV - 1) + t;
        if (ls >= 0) {
            const __half* xp = g_xih + (size_t)(m - (DCONV - 1) + t) * DINNER + c;
            __half2 h0 = *reinterpret_cast<const __half2*>(xp);
            __half2 h1 = *reinterpret_cast<const __half2*>(xp + 2);
            float2 f0 = __half22float2(h0);
            float2 f1 = __half22float2(h1);
            a0 = fmaf(w[0][t], f0.x, a0);
            a1 = fmaf(w[1][t], f0.y, a1);
            a2 = fmaf(w[2][t], f1.x, a2);
            a3 = fmaf(w[3][t], f1.y, a3);
        }
    }
    float4 o;
    o.x = a0 / (1.f + expf(-a0));
    o.y = a1 / (1.f + expf(-a1));
    o.z = a2 / (1.f + expf(-a2));
    o.w = a3 / (1.f + expf(-a3));
    *reinterpret_cast<float4*>(g_xa + (size_t)m * DINNER + c) = o;
    __half* hp = g_xah + (size_t)m * DINNER + c;
    *reinterpret_cast<__half2*>(hp)     = __floats2half2_rn(o.x, o.y);
    *reinterpret_cast<__half2*>(hp + 2) = __floats2half2_rn(o.z, o.w);
}

__global__ void u_kernel()
{
    int gw = (blockIdx.x * blockDim.x + threadIdx.x) >> 5;
    int lane = threadIdx.x & 31;
    if (gw >= M_TOK) return;
    const float* xa = g_xa + (size_t)gw * DINNER;
    float v = xa[lane] + xa[lane + 32];
#pragma unroll
    for (int o = 16; o; o >>= 1) v += __shfl_down_sync(0xffffffffu, v, o);
    if (lane == 0) g_u[gw] = v * (1.f / 64.f);
}

__global__ void dtbu_kernel(const float* __restrict__ bdt, const float* __restrict__ Alog)
{
    int idx = blockIdx.x * blockDim.x + threadIdx.x;
    int m = idx >> 4;
    int n = idx & (DSTATE - 1);
    float raw = g_dtb[(size_t)m * 2 * DSTATE + n] + bdt[n];
    float dt  = raw > 20.f ? raw : log1pf(expf(raw));
    float bp  = g_dtb[(size_t)m * 2 * DSTATE + DSTATE + n];
    float A   = -expf(Alog[n]);
    g_adisc[idx] = expf(A * dt);
    g_bu[idx]    = dt * bp * g_u[m];
}

// -------- chunked scan (3 passes) --------
__global__ void scan_part_kernel()
{
    int t = blockIdx.x * blockDim.x + threadIdx.x;
    int chain = t >> 5, c = t & 31;
    int b = chain >> 4, n = chain & 15;
    size_t base = ((size_t)(b * SEQLEN + c * SCHUNK)) * DSTATE + n;
    float A = 1.f, V = 0.f;
#pragma unroll 8
    for (int i = 0; i < SCHUNK; i++) {
        float a = g_adisc[base + (size_t)i * DSTATE];
        float v = g_bu   [base + (size_t)i * DSTATE];
        V = fmaf(a, V, v);
        A *= a;
    }
    g_cA[chain * NCHUNK + c] = A;
    g_cV[chain * NCHUNK + c] = V;
}
__global__ void scan_mid_kernel()
{
    int chain = threadIdx.x;
    float s = 0.f;
#pragma unroll
    for (int c = 0; c < NCHUNK; c++) {
        g_carry[chain * NCHUNK + c] = s;
        s = fmaf(g_cA[chain * NCHUNK + c], s, g_cV[chain * NCHUNK + c]);
    }
}
__global__ void scan_apply_kernel()
{
    int t = blockIdx.x * blockDim.x + threadIdx.x;
    int chain = t >> 5, c = t & 31;
    int b = chain >> 4, n = chain & 15;
    size_t base = ((size_t)(b * SEQLEN + c * SCHUNK)) * DSTATE + n;
    float s = g_carry[chain * NCHUNK + c];
#pragma unroll 8
    for (int i = 0; i < SCHUNK; i++) {
        float a = g_adisc[base + (size_t)i * DSTATE];
        float v = g_bu   [base + (size_t)i * DSTATE];
        s = fmaf(a, s, v);
        g_y[base + (size_t)i * DSTATE] = s;
    }
}

// -------- gate + skip -> fp16 y_full -----------------------------------------
__global__ void elt_kernel(const float* __restrict__ Dp)
{
    int idx = blockIdx.x * blockDim.x + threadIdx.x;
    int c4 = idx & (DINNER/4 - 1);
    int m  = idx >> 8;
    int c  = c4 * 4;
    float yv  = g_y[(size_t)m * DSTATE + (c >> 6)];
    float4 xa = *reinterpret_cast<const float4*>(g_xa + (size_t)m * DINNER + c);
    float4 D  = *reinterpret_cast<const float4*>(Dp + c);
    const __half* rp = g_resh + (size_t)m * DINNER + c;
    float2 r0 = __half22float2(*reinterpret_cast<const __half2*>(rp));
    float2 r1 = __half22float2(*reinterpret_cast<const __half2*>(rp + 2));
    float o0 = (yv + xa.x * D.x) * r0.x;
    float o1 = (yv + xa.y * D.y) * r0.y;
    float o2 = (yv + xa.z * D.z) * r1.x;
    float o3 = (yv + xa.w * D.w) * r1.y;
    __half* row = g_yh + (size_t)m * DINNER + c;
    *reinterpret_cast<__half2*>(row)     = __floats2half2_rn(o0, o1);
    *reinterpret_cast<__half2*>(row + 2) = __floats2half2_rn(o2, o3);
}

// ======================= launch ==============================================
extern "C" void kernel_launch(void* const* d_in, const int* in_sizes, int n_in,
                              void* d_out, int out_size)
{
    const float* x      = (const float*)d_in[0];
    const float* W_in   = (const float*)d_in[1];
    const float* conv_w = (const float*)d_in[2];
    const float* conv_b = (const float*)d_in[3];
    const float* W_x    = (const float*)d_in[4];
    const float* W_dt   = (const float*)d_in[5];
    const float* b_dt   = (const float*)d_in[6];
    const float* A_log  = (const float*)d_in[7];
    const float* D_par  = (const float*)d_in[8];
    const float* W_out  = (const float*)d_in[9];
    float* out = (float*)d_out;

    float* dtb;  cudaGetSymbolAddress((void**)&dtb,  g_dtb);
    __half* xh;  cudaGetSymbolAddress((void**)&xh,  g_xh);
    __half* xah; cudaGetSymbolAddress((void**)&xah, g_xah);
    __half* yh;  cudaGetSymbolAddress((void**)&yh,  g_yh);
    __half* wih; cudaGetSymbolAddress((void**)&wih, g_wih);
    __half* woh; cudaGetSymbolAddress((void**)&woh, g_woh);
    __half* wch; cudaGetSymbolAddress((void**)&wch, g_wch);

    cudaFuncSetAttribute(gemm_hmma<0>, cudaFuncAttributeMaxDynamicSharedMemorySize, GH_SMEM);
    cudaFuncSetAttribute(gemm_hmma<1>, cudaFuncAttributeMaxDynamicSharedMemorySize, GH_SMEM);
    cudaFuncSetAttribute(gemm_small,   cudaFuncAttributeMaxDynamicSharedMemorySize, GS_SMEM);

    // weight / input conversion to fp16
    wcat_kernel<<<(2*DSTATE*DINNER)/256, 256>>>(W_x, W_dt);
    tohalf_kernel<<<(2*DINNER*DIM)/1024, 256>>>(W_in, wih);
    tohalf_kernel<<<(DIM*DINNER)/1024, 256>>>(W_out, woh);
    tohalf_kernel<<<((long)M_TOK*DIM)/1024, 256>>>(x, xh);

    // GEMM1 (fused split epilogue): xi -> g_xih, silu(res) -> g_resh
    gemm_hmma<1><<<dim3(2*DINNER/128, M_TOK/128), 256, GH_SMEM>>>(
        xh, wih, nullptr, 2*DINNER, DIM);

    conv_silu_kernel<<<(M_TOK*(DINNER/4))/256, 256>>>(conv_w, conv_b);
    u_kernel<<<(M_TOK*32)/256, 256>>>();

    // small GEMM (HMMA): dtb = xa_h @ wcat_h^T  [16384 x 32 x 1024]
    gemm_small<<<M_TOK/128, 256, GS_SMEM>>>(xah, wch, dtb);

    dtbu_kernel<<<(M_TOK*DSTATE)/256, 256>>>(b_dt, A_log);

    scan_part_kernel<<<(BATCH*DSTATE*NCHUNK)/256, 256>>>();
    scan_mid_kernel<<<1, BATCH*DSTATE>>>();
    scan_apply_kernel<<<(BATCH*DSTATE*NCHUNK)/256, 256>>>();

    elt_kernel<<<(M_TOK*(DINNER/4))/256, 256>>>(D_par);

    // GEMM2: out = y_full @ W_out^T  [16384 x 512 x 1024]
    gemm_hmma<0><<<dim3(DIM/128, M_TOK/128), 256, GH_SMEM>>>(
        yh, woh, out, DIM, DINNER);
}

// round 11
// speedup vs baseline: 1.2070x; 1.0466x over previous
#include <cuda_runtime.h>
#include <cuda_fp16.h>
#include <math.h>
#include <stdint.h>

#define BATCH   4
#define SEQLEN  4096
#define DIM     512
#define DINNER  1024
#define DSTATE  16
#define DCONV   4
#define M_TOK   (BATCH*SEQLEN)   // 16384

// ======================= PTX helpers (sm_80 baseline) ========================
__device__ __forceinline__ uint32_t smem_to_u32(const void* p) {
    uint32_t a;
    asm("{ .reg .u64 t; cvta.to.shared.u64 t, %1; cvt.u32.u64 %0, t; }"
        : "=r"(a) : "l"(p));
    return a;
}
#define CP_ASYNC16(saddr, gptr) \
    asm volatile("cp.async.cg.shared.global [%0], [%1], 16;" \
        :: "r"(saddr), "l"(gptr))
#define CP_COMMIT() asm volatile("cp.async.commit_group;" ::: "memory")
#define CP_WAIT1()  asm volatile("cp.async.wait_group 1;" ::: "memory")
#define CP_WAIT0()  asm volatile("cp.async.wait_group 0;" ::: "memory")

#define LDSM_X4(r, addr) \
    asm volatile("ldmatrix.sync.aligned.m8n8.x4.shared.b16 {%0,%1,%2,%3}, [%4];" \
        : "=r"((r)[0]), "=r"((r)[1]), "=r"((r)[2]), "=r"((r)[3]) : "r"(addr))

#define MMA_F16(d, a, b0, b1) \
    asm volatile("mma.sync.aligned.m16n8k16.row.col.f32.f16.f16.f32 " \
        "{%0,%1,%2,%3}, {%4,%5,%6,%7}, {%8,%9}, {%0,%1,%2,%3};" \
        : "+f"((d)[0]), "+f"((d)[1]), "+f"((d)[2]), "+f"((d)[3]) \
        : "r"((a)[0]), "r"((a)[1]), "r"((a)[2]), "r"((a)[3]), "r"(b0), "r"(b1))

// ======================= scratch =============================================
__device__ __align__(256) float  g_u   [M_TOK];
__device__ __align__(256) float  g_adisc[(size_t)M_TOK * DSTATE];
__device__ __align__(256) float  g_bu  [(size_t)M_TOK * DSTATE];
__device__ __align__(256) float  g_y   [(size_t)M_TOK * DSTATE];
// fp16 planes
__device__ __align__(256) __half g_xh  [(size_t)M_TOK * DIM];       // x
__device__ __align__(256) __half g_xih [(size_t)M_TOK * DINNER];    // xi (GEMM1 out)
__device__ __align__(256) __half g_resh[(size_t)M_TOK * DINNER];    // silu(res)
__device__ __align__(256) __half g_xah [(size_t)M_TOK * DINNER];    // xa fp16
__device__ __align__(256) __half g_yh  [(size_t)M_TOK * DINNER];    // y_full
__device__ __align__(256) __half g_wih [(size_t)2*DINNER * DIM];
__device__ __align__(256) __half g_woh [(size_t)DIM * DINNER];
__device__ __align__(256) __half g_wch [2 * DSTATE * DINNER];       // [W_dt;W_x(16:32)]
// scan chunk summaries
#define SCHUNK  128
#define NCHUNK  (SEQLEN / SCHUNK)   // 32
__device__ float g_cA   [BATCH * DSTATE * NCHUNK];
__device__ float g_cV   [BATCH * DSTATE * NCHUNK];
__device__ float g_carry[BATCH * DSTATE * NCHUNK];

// ======================= HMMA fp16 GEMM (R7 config) ==========================
// Block tile 128x128, 256 threads (8 warps 4x2, warp tile 32x64),
// K-chunk 64, cp.async double buffer.
// MODE 0: fp32 C. MODE 1: GEMM1 split epilogue -> g_xih / g_resh.
#define LG_ROWB   144
#define LG_TILE_B (128 * LG_ROWB)          // 18432 B
#define GH_SMEM   (4 * LG_TILE_B)          // 73728 B

template<int MODE>
__global__ __launch_bounds__(256, 2)
void gemm_hmma(const __half* __restrict__ A, const __half* __restrict__ B,
               float* __restrict__ C, int Nglob, int K)
{
    extern __shared__ char smem[];
    const uint32_t sb = smem_to_u32(smem);
    const int tid  = threadIdx.x;
    const int wid  = tid >> 5;
    const int lane = tid & 31;
    const int m0 = blockIdx.y * 128;
    const int n0 = blockIdx.x * 128;
    const int nch = K / 64;

    const int wm = (wid & 3) * 32;
    const int wn = (wid >> 2) * 64;
    const uint32_t offA[2] = { 0u,              2u * LG_TILE_B };
    const uint32_t offB[2] = { (uint32_t)LG_TILE_B, 3u * LG_TILE_B };

    float acc[2][8][4];
#pragma unroll
    for (int i = 0; i < 2; i++)
#pragma unroll
        for (int j = 0; j < 8; j++)
#pragma unroll
            for (int k = 0; k < 4; k++) acc[i][j][k] = 0.f;

    auto issue = [&](int c, int b) {
        const __half* Ag = A + (size_t)m0 * K + (size_t)c * 64;
        const __half* Bg = B + (size_t)n0 * K + (size_t)c * 64;
        const uint32_t sa  = sb + offA[b];
        const uint32_t sbm = sb + offB[b];
#pragma unroll
        for (int i = 0; i < 4; i++) {
            int idx = tid + i * 256;
            int row = idx >> 3, cc = idx & 7;
            CP_ASYNC16(sa  + (uint32_t)(row * LG_ROWB + cc * 16),
                       Ag + (size_t)row * K + cc * 8);
            CP_ASYNC16(sbm + (uint32_t)(row * LG_ROWB + cc * 16),
                       Bg + (size_t)row * K + cc * 8);
        }
        CP_COMMIT();
    };

    issue(0, 0);
    for (int c = 0; c < nch; c++) {
        const int buf = c & 1;
        if (c + 1 < nch) { issue(c + 1, buf ^ 1); CP_WAIT1(); }
        else             { CP_WAIT0(); }
        __syncthreads();

        const uint32_t aBase = sb + offA[buf];
        const uint32_t bBase = sb + offB[buf];
        const int lrow = lane & 15;
        const int lcol = (lane >> 4) * 16;
#pragma unroll
        for (int ks = 0; ks < 4; ks++) {
            uint32_t af[2][4], bfr[4][4];
#pragma unroll
            for (int mt = 0; mt < 2; mt++)
                LDSM_X4(af[mt], aBase + (uint32_t)((wm + mt*16 + lrow) * LG_ROWB + ks*32 + lcol));
#pragma unroll
            for (int ng = 0; ng < 4; ng++)
                LDSM_X4(bfr[ng], bBase + (uint32_t)((wn + ng*16 + lrow) * LG_ROWB + ks*32 + lcol));
#pragma unroll
            for (int mt = 0; mt < 2; mt++)
#pragma unroll
                for (int nt = 0; nt < 8; nt++) {
                    const int ng = nt >> 1, hi = nt & 1;
                    MMA_F16(acc[mt][nt], af[mt], bfr[ng][hi], bfr[ng][2 + hi]);
                }
        }
        __syncthreads();
    }

    const int er = lane >> 2;
    const int ec = (lane & 3) * 2;
    if (MODE == 0) {
#pragma unroll
        for (int mt = 0; mt < 2; mt++) {
            const int rbase = m0 + wm + mt * 16;
#pragma unroll
            for (int nt = 0; nt < 8; nt++) {
                const int col = n0 + wn + nt * 8 + ec;
                *reinterpret_cast<float2*>(C + (size_t)(rbase + er)     * Nglob + col) =
                    make_float2(acc[mt][nt][0], acc[mt][nt][1]);
                *reinterpret_cast<float2*>(C + (size_t)(rbase + er + 8) * Nglob + col) =
                    make_float2(acc[mt][nt][2], acc[mt][nt][3]);
            }
        }
    } else {
        const bool isRes = (n0 >= DINNER);
#pragma unroll
        for (int mt = 0; mt < 2; mt++) {
            const int rbase = m0 + wm + mt * 16;
#pragma unroll
            for (int nt = 0; nt < 8; nt++) {
                int col = n0 + wn + nt * 8 + ec;
                float v0 = acc[mt][nt][0], v1 = acc[mt][nt][1];
                float v2 = acc[mt][nt][2], v3 = acc[mt][nt][3];
                if (isRes) {
                    col -= DINNER;
                    v0 = v0 / (1.f + expf(-v0));
                    v1 = v1 / (1.f + expf(-v1));
                    v2 = v2 / (1.f + expf(-v2));
                    v3 = v3 / (1.f + expf(-v3));
                    *reinterpret_cast<__half2*>(g_resh + (size_t)(rbase + er)     * DINNER + col) =
                        __floats2half2_rn(v0, v1);
                    *reinterpret_cast<__half2*>(g_resh + (size_t)(rbase + er + 8) * DINNER + col) =
                        __floats2half2_rn(v2, v3);
                } else {
                    *reinterpret_cast<__half2*>(g_xih + (size_t)(rbase + er)     * DINNER + col) =
                        __floats2half2_rn(v0, v1);
                    *reinterpret_cast<__half2*>(g_xih + (size_t)(rbase + er + 8) * DINNER + col) =
                        __floats2half2_rn(v2, v3);
                }
            }
        }
    }
}

// ============== small HMMA GEMM fused with dt/A_disc/Bu epilogue =============
// adisc/bu = f(xa_h @ wcat_h^T). M=16384, N=32, K=1024.
// Block 128(M)x32(N), 256 thr (8 warps, warp 16x32). B resident in smem.
#define SB_ROWB   2064
#define SB_BYTES  (32 * SB_ROWB)              // 66048
#define SA_TILE   (128 * LG_ROWB)             // 18432
#define GS_SMEM   (SB_BYTES + 2 * SA_TILE)    // 102912

__global__ __launch_bounds__(256, 1)
void gemm_small(const __half* __restrict__ A, const __half* __restrict__ B,
                const float* __restrict__ bdt, const float* __restrict__ Alog)
{
    extern __shared__ char smem[];
    const uint32_t sb = smem_to_u32(smem);
    const int tid  = threadIdx.x;
    const int wid  = tid >> 5;
    const int lane = tid & 31;
    const int m0 = blockIdx.x * 128;
    const int K = DINNER;
    const int nch = K / 64;

    {
#pragma unroll
        for (int i = 0; i < 16; i++) {
            int idx = tid + i * 256;
            int row = idx >> 7, cc = idx & 127;
            CP_ASYNC16(sb + (uint32_t)(row * SB_ROWB + cc * 16),
                       B + (size_t)row * K + cc * 8);
        }
        CP_COMMIT();
    }
    const uint32_t offA[2] = { (uint32_t)SB_BYTES, (uint32_t)(SB_BYTES + SA_TILE) };

    auto issueA = [&](int c, int b) {
        const __half* Ag = A + (size_t)m0 * K + (size_t)c * 64;
        const uint32_t sa = sb + offA[b];
#pragma unroll
        for (int i = 0; i < 4; i++) {
            int idx = tid + i * 256;
            int row = idx >> 3, cc = idx & 7;
            CP_ASYNC16(sa + (uint32_t)(row * LG_ROWB + cc * 16),
                       Ag + (size_t)row * K + cc * 8);
        }
        CP_COMMIT();
    };

    const int wm = wid * 16;
    float acc[4][4];
#pragma unroll
    for (int j = 0; j < 4; j++)
#pragma unroll
        for (int k = 0; k < 4; k++) acc[j][k] = 0.f;

    issueA(0, 0);
    for (int c = 0; c < nch; c++) {
        const int buf = c & 1;
        if (c + 1 < nch) { issueA(c + 1, buf ^ 1); CP_WAIT1(); }
        else             { CP_WAIT0(); }
        __syncthreads();

        const uint32_t aBase = sb + offA[buf];
        const int lrow = lane & 15;
        const int lcol = (lane >> 4) * 16;
#pragma unroll
        for (int ks = 0; ks < 4; ks++) {
            uint32_t af[4], bfr[2][4];
            LDSM_X4(af, aBase + (uint32_t)((wm + lrow) * LG_ROWB + ks*32 + lcol));
#pragma unroll
            for (int ng = 0; ng < 2; ng++)
                LDSM_X4(bfr[ng], sb + (uint32_t)((ng*16 + lrow) * SB_ROWB + (c*4 + ks)*32 + lcol));
#pragma unroll
            for (int nt = 0; nt < 4; nt++) {
                const int ng = nt >> 1, hi = nt & 1;
                MMA_F16(acc[nt], af, bfr[ng][hi], bfr[ng][2 + hi]);
            }
        }
        __syncthreads();
    }

    // fused epilogue: cols 0..15 = dt_raw (nt 0,1), cols 16..31 = B_proj (nt 2,3)
    const int er = lane >> 2;
    const int ec = (lane & 3) * 2;
    const int r0 = m0 + wm + er;
    const float u0 = g_u[r0];
    const float u1 = g_u[r0 + 8];
#pragma unroll
    for (int nt = 0; nt < 2; nt++) {
#pragma unroll
        for (int j = 0; j < 2; j++) {
            const int n = nt * 8 + ec + j;
            const float A = -expf(Alog[n]);
            const float bn = bdt[n];
            // row r0 (regs j), row r0+8 (regs 2+j)
            {
                float raw = acc[nt][j] + bn;
                float dt  = raw > 20.f ? raw : log1pf(expf(raw));
                g_adisc[(size_t)r0 * DSTATE + n] = expf(A * dt);
                g_bu   [(size_t)r0 * DSTATE + n] = dt * acc[nt + 2][j] * u0;
            }
            {
                float raw = acc[nt][2 + j] + bn;
                float dt  = raw > 20.f ? raw : log1pf(expf(raw));
                g_adisc[(size_t)(r0 + 8) * DSTATE + n] = expf(A * dt);
                g_bu   [(size_t)(r0 + 8) * DSTATE + n] = dt * acc[nt + 2][2 + j] * u1;
            }
        }
    }
}

// ======================= conversions / pointwise =============================
__global__ void tohalf_kernel(const float* __restrict__ src, __half* __restrict__ dst)
{
    long i = ((long)blockIdx.x * blockDim.x + threadIdx.x) * 4;
    float4 v = *reinterpret_cast<const float4*>(src + i);
    *reinterpret_cast<__half2*>(dst + i)     = __floats2half2_rn(v.x, v.y);
    *reinterpret_cast<__half2*>(dst + i + 2) = __floats2half2_rn(v.z, v.w);
}

__global__ void wcat_kernel(const float* __restrict__ Wx, const float* __restrict__ Wdt)
{
    int idx = blockIdx.x * blockDim.x + threadIdx.x;
    int row = idx >> 10;
    float v = (row < DSTATE) ? Wdt[idx] : Wx[idx];
    g_wch[idx] = __float2half_rn(v);
}

// conv(4)+bias+SiLU (fp16 in/out) with fused u (block = one token)
__global__ void conv_silu_kernel(const float* __restrict__ cw, const float* __restrict__ cb)
{
    const int m  = blockIdx.x;            // token
    const int c4 = threadIdx.x;           // 0..255
    const int c  = c4 * 4;
    const int l  = m & (SEQLEN - 1);

    float w[4][4];
#pragma unroll
    for (int j = 0; j < 4; j++)
        *reinterpret_cast<float4*>(w[j]) =
            *reinterpret_cast<const float4*>(cw + (size_t)(c + j) * DCONV);
    float4 b = *reinterpret_cast<const float4*>(cb + c);
    float a0 = b.x, a1 = b.y, a2 = b.z, a3 = b.w;
#pragma unroll
    for (int t = 0; t < DCONV; t++) {
        int ls = l - (DCONV - 1) + t;
        if (ls >= 0) {
            const __half* xp = g_xih + (size_t)(m - (DCONV - 1) + t) * DINNER + c;
            float2 f0 = __half22float2(*reinterpret_cast<const __half2*>(xp));
            float2 f1 = __half22float2(*reinterpret_cast<const __half2*>(xp + 2));
            a0 = fmaf(w[0][t], f0.x, a0);
            a1 = fmaf(w[1][t], f0.y, a1);
            a2 = fmaf(w[2][t], f1.x, a2);
            a3 = fmaf(w[3][t], f1.y, a3);
        }
    }
    float o0 = a0 / (1.f + expf(-a0));
    float o1 = a1 / (1.f + expf(-a1));
    float o2 = a2 / (1.f + expf(-a2));
    float o3 = a3 / (1.f + expf(-a3));
    __half* hp = g_xah + (size_t)m * DINNER + c;
    *reinterpret_cast<__half2*>(hp)     = __floats2half2_rn(o0, o1);
    *reinterpret_cast<__half2*>(hp + 2) = __floats2half2_rn(o2, o3);

    // fused u: channels 0..63 live in lanes 0..15 of warp 0
    if (c4 < 16) {
        float s = o0 + o1 + o2 + o3;
#pragma unroll
        for (int o = 8; o; o >>= 1) s += __shfl_down_sync(0xffffu, s, o);
        if (c4 == 0) g_u[m] = s * (1.f / 64.f);
    }
}

// -------- chunked scan (3 passes) --------
__global__ void scan_part_kernel()
{
    int t = blockIdx.x * blockDim.x + threadIdx.x;
    int chain = t >> 5, c = t & 31;
    int b = chain >> 4, n = chain & 15;
    size_t base = ((size_t)(b * SEQLEN + c * SCHUNK)) * DSTATE + n;
    float A = 1.f, V = 0.f;
#pragma unroll 8
    for (int i = 0; i < SCHUNK; i++) {
        float a = g_adisc[base + (size_t)i * DSTATE];
        float v = g_bu   [base + (size_t)i * DSTATE];
        V = fmaf(a, V, v);
        A *= a;
    }
    g_cA[chain * NCHUNK + c] = A;
    g_cV[chain * NCHUNK + c] = V;
}
__global__ void scan_mid_kernel()
{
    int chain = threadIdx.x;
    float s = 0.f;
#pragma unroll
    for (int c = 0; c < NCHUNK; c++) {
        g_carry[chain * NCHUNK + c] = s;
        s = fmaf(g_cA[chain * NCHUNK + c], s, g_cV[chain * NCHUNK + c]);
    }
}
__global__ void scan_apply_kernel()
{
    int t = blockIdx.x * blockDim.x + threadIdx.x;
    int chain = t >> 5, c = t & 31;
    int b = chain >> 4, n = chain & 15;
    size_t base = ((size_t)(b * SEQLEN + c * SCHUNK)) * DSTATE + n;
    float s = g_carry[chain * NCHUNK + c];
#pragma unroll 8
    for (int i = 0; i < SCHUNK; i++) {
        float a = g_adisc[base + (size_t)i * DSTATE];
        float v = g_bu   [base + (size_t)i * DSTATE];
        s = fmaf(a, s, v);
        g_y[base + (size_t)i * DSTATE] = s;
    }
}

// -------- gate + skip -> fp16 y_full (all-fp16 inputs) ------------------------
__global__ void elt_kernel(const float* __restrict__ Dp)
{
    int idx = blockIdx.x * blockDim.x + threadIdx.x;
    int c4 = idx & (DINNER/4 - 1);
    int m  = idx >> 8;
    int c  = c4 * 4;
    float yv  = g_y[(size_t)m * DSTATE + (c >> 6)];
    const __half* xp = g_xah + (size_t)m * DINNER + c;
    float2 x0 = __half22float2(*reinterpret_cast<const __half2*>(xp));
    float2 x1 = __half22float2(*reinterpret_cast<const __half2*>(xp + 2));
    float4 D  = *reinterpret_cast<const float4*>(Dp + c);
    const __half* rp = g_resh + (size_t)m * DINNER + c;
    float2 r0 = __half22float2(*reinterpret_cast<const __half2*>(rp));
    float2 r1 = __half22float2(*reinterpret_cast<const __half2*>(rp + 2));
    float o0 = (yv + x0.x * D.x) * r0.x;
    float o1 = (yv + x0.y * D.y) * r0.y;
    float o2 = (yv + x1.x * D.z) * r1.x;
    float o3 = (yv + x1.y * D.w) * r1.y;
    __half* row = g_yh + (size_t)m * DINNER + c;
    *reinterpret_cast<__half2*>(row)     = __floats2half2_rn(o0, o1);
    *reinterpret_cast<__half2*>(row + 2) = __floats2half2_rn(o2, o3);
}

// ======================= launch ==============================================
extern "C" void kernel_launch(void* const* d_in, const int* in_sizes, int n_in,
                              void* d_out, int out_size)
{
    const float* x      = (const float*)d_in[0];
    const float* W_in   = (const float*)d_in[1];
    const float* conv_w = (const float*)d_in[2];
    const float* conv_b = (const float*)d_in[3];
    const float* W_x    = (const float*)d_in[4];
    const float* W_dt   = (const float*)d_in[5];
    const float* b_dt   = (const float*)d_in[6];
    const float* A_log  = (const float*)d_in[7];
    const float* D_par  = (const float*)d_in[8];
    const float* W_out  = (const float*)d_in[9];
    float* out = (float*)d_out;

    __half* xh;  cudaGetSymbolAddress((void**)&xh,  g_xh);
    __half* xah; cudaGetSymbolAddress((void**)&xah, g_xah);
    __half* yh;  cudaGetSymbolAddress((void**)&yh,  g_yh);
    __half* wih; cudaGetSymbolAddress((void**)&wih, g_wih);
    __half* woh; cudaGetSymbolAddress((void**)&woh, g_woh);
    __half* wch; cudaGetSymbolAddress((void**)&wch, g_wch);

    cudaFuncSetAttribute(gemm_hmma<0>, cudaFuncAttributeMaxDynamicSharedMemorySize, GH_SMEM);
    cudaFuncSetAttribute(gemm_hmma<1>, cudaFuncAttributeMaxDynamicSharedMemorySize, GH_SMEM);
    cudaFuncSetAttribute(gemm_small,   cudaFuncAttributeMaxDynamicSharedMemorySize, GS_SMEM);

    wcat_kernel<<<(2*DSTATE*DINNER)/256, 256>>>(W_x, W_dt);
    tohalf_kernel<<<(2*DINNER*DIM)/1024, 256>>>(W_in, wih);
    tohalf_kernel<<<(DIM*DINNER)/1024, 256>>>(W_out, woh);
    tohalf_kernel<<<((long)M_TOK*DIM)/1024, 256>>>(x, xh);

    // GEMM1 (fused split epilogue): xi -> g_xih, silu(res) -> g_resh
    gemm_hmma<1><<<dim3(2*DINNER/128, M_TOK/128), 256, GH_SMEM>>>(
        xh, wih, nullptr, 2*DINNER, DIM);

    // conv+SiLU+u (block = token)
    conv_silu_kernel<<<M_TOK, 256>>>(conv_w, conv_b);

    // small GEMM + fused dt/A_disc/Bu epilogue
    gemm_small<<<M_TOK/128, 256, GS_SMEM>>>(xah, wch, b_dt, A_log);

    scan_part_kernel<<<(BATCH*DSTATE*NCHUNK)/256, 256>>>();
    scan_mid_kernel<<<1, BATCH*DSTATE>>>();
    scan_apply_kernel<<<(BATCH*DSTATE*NCHUNK)/256, 256>>>();

    elt_kernel<<<(M_TOK*(DINNER/4))/256, 256>>>(D_par);

    // GEMM2: out = y_full @ W_out^T
    gemm_hmma<0><<<dim3(DIM/128, M_TOK/128), 256, GH_SMEM>>>(
        yh, woh, out, DIM, DINNER);
}

// round 12
// speedup vs baseline: 1.4530x; 1.2038x over previous
#include <cuda_runtime.h>
#include <cuda_fp16.h>
#include <math.h>
#include <stdint.h>

#define BATCH   4
#define SEQLEN  4096
#define DIM     512
#define DINNER  1024
#define DSTATE  16
#define DCONV   4
#define M_TOK   (BATCH*SEQLEN)   // 16384

// ======================= PTX helpers (sm_80 baseline) ========================
__device__ __forceinline__ uint32_t smem_to_u32(const void* p) {
    uint32_t a;
    asm("{ .reg .u64 t; cvta.to.shared.u64 t, %1; cvt.u32.u64 %0, t; }"
        : "=r"(a) : "l"(p));
    return a;
}
#define CP_ASYNC16(saddr, gptr) \
    asm volatile("cp.async.cg.shared.global [%0], [%1], 16;" \
        :: "r"(saddr), "l"(gptr))
#define CP_COMMIT() asm volatile("cp.async.commit_group;" ::: "memory")
#define CP_WAIT1()  asm volatile("cp.async.wait_group 1;" ::: "memory")
#define CP_WAIT0()  asm volatile("cp.async.wait_group 0;" ::: "memory")

#define LDSM_X4(r, addr) \
    asm volatile("ldmatrix.sync.aligned.m8n8.x4.shared.b16 {%0,%1,%2,%3}, [%4];" \
        : "=r"((r)[0]), "=r"((r)[1]), "=r"((r)[2]), "=r"((r)[3]) : "r"(addr))

#define MMA_F16(d, a, b0, b1) \
    asm volatile("mma.sync.aligned.m16n8k16.row.col.f32.f16.f16.f32 " \
        "{%0,%1,%2,%3}, {%4,%5,%6,%7}, {%8,%9}, {%0,%1,%2,%3};" \
        : "+f"((d)[0]), "+f"((d)[1]), "+f"((d)[2]), "+f"((d)[3]) \
        : "r"((a)[0]), "r"((a)[1]), "r"((a)[2]), "r"((a)[3]), "r"(b0), "r"(b1))

// ======================= scratch =============================================
__device__ __align__(256) float  g_u   [M_TOK];
__device__ __align__(256) float  g_adisc[(size_t)M_TOK * DSTATE];
__device__ __align__(256) float  g_bu  [(size_t)M_TOK * DSTATE];
__device__ __align__(256) float  g_y   [(size_t)M_TOK * DSTATE];
// fp16 planes
__device__ __align__(256) __half g_xh  [(size_t)M_TOK * DIM];
__device__ __align__(256) __half g_xih [(size_t)M_TOK * DINNER];
__device__ __align__(256) __half g_resh[(size_t)M_TOK * DINNER];
__device__ __align__(256) __half g_xah [(size_t)M_TOK * DINNER];
__device__ __align__(256) __half g_yh  [(size_t)M_TOK * DINNER];
__device__ __align__(256) __half g_wih [(size_t)2*DINNER * DIM];
__device__ __align__(256) __half g_woh [(size_t)DIM * DINNER];
__device__ __align__(256) __half g_wch [2 * DSTATE * DINNER];
// scan constants
#define SCHUNK  128
#define NCHUNK  (SEQLEN / SCHUNK)   // 32

// ======================= HMMA fp16 GEMM ======================================
// Block tile 128x128, 256 threads (8 warps 4x2, warp tile 32x64),
// K-chunk 64, cp.async double buffer.
// MODE 0: fp32 C (Nglob stride). MODE 1: write g_xih. MODE 2: silu -> g_resh.
#define LG_ROWB   144
#define LG_TILE_B (128 * LG_ROWB)          // 18432 B
#define GH_SMEM   (4 * LG_TILE_B)          // 73728 B

template<int MODE>
__global__ __launch_bounds__(256, 2)
void gemm_hmma(const __half* __restrict__ A, const __half* __restrict__ B,
               float* __restrict__ C, int Nglob, int K)
{
    extern __shared__ char smem[];
    const uint32_t sb = smem_to_u32(smem);
    const int tid  = threadIdx.x;
    const int wid  = tid >> 5;
    const int lane = tid & 31;
    const int m0 = blockIdx.y * 128;
    const int n0 = blockIdx.x * 128;
    const int nch = K / 64;

    const int wm = (wid & 3) * 32;
    const int wn = (wid >> 2) * 64;
    const uint32_t offA[2] = { 0u,              2u * LG_TILE_B };
    const uint32_t offB[2] = { (uint32_t)LG_TILE_B, 3u * LG_TILE_B };

    float acc[2][8][4];
#pragma unroll
    for (int i = 0; i < 2; i++)
#pragma unroll
        for (int j = 0; j < 8; j++)
#pragma unroll
            for (int k = 0; k < 4; k++) acc[i][j][k] = 0.f;

    auto issue = [&](int c, int b) {
        const __half* Ag = A + (size_t)m0 * K + (size_t)c * 64;
        const __half* Bg = B + (size_t)n0 * K + (size_t)c * 64;
        const uint32_t sa  = sb + offA[b];
        const uint32_t sbm = sb + offB[b];
#pragma unroll
        for (int i = 0; i < 4; i++) {
            int idx = tid + i * 256;
            int row = idx >> 3, cc = idx & 7;
            CP_ASYNC16(sa  + (uint32_t)(row * LG_ROWB + cc * 16),
                       Ag + (size_t)row * K + cc * 8);
            CP_ASYNC16(sbm + (uint32_t)(row * LG_ROWB + cc * 16),
                       Bg + (size_t)row * K + cc * 8);
        }
        CP_COMMIT();
    };

    issue(0, 0);
    for (int c = 0; c < nch; c++) {
        const int buf = c & 1;
        if (c + 1 < nch) { issue(c + 1, buf ^ 1); CP_WAIT1(); }
        else             { CP_WAIT0(); }
        __syncthreads();

        const uint32_t aBase = sb + offA[buf];
        const uint32_t bBase = sb + offB[buf];
        const int lrow = lane & 15;
        const int lcol = (lane >> 4) * 16;
#pragma unroll
        for (int ks = 0; ks < 4; ks++) {
            uint32_t af[2][4], bfr[4][4];
#pragma unroll
            for (int mt = 0; mt < 2; mt++)
                LDSM_X4(af[mt], aBase + (uint32_t)((wm + mt*16 + lrow) * LG_ROWB + ks*32 + lcol));
#pragma unroll
            for (int ng = 0; ng < 4; ng++)
                LDSM_X4(bfr[ng], bBase + (uint32_t)((wn + ng*16 + lrow) * LG_ROWB + ks*32 + lcol));
#pragma unroll
            for (int mt = 0; mt < 2; mt++)
#pragma unroll
                for (int nt = 0; nt < 8; nt++) {
                    const int ng = nt >> 1, hi = nt & 1;
                    MMA_F16(acc[mt][nt], af[mt], bfr[ng][hi], bfr[ng][2 + hi]);
                }
        }
        __syncthreads();
    }

    const int er = lane >> 2;
    const int ec = (lane & 3) * 2;
#pragma unroll
    for (int mt = 0; mt < 2; mt++) {
        const int rbase = m0 + wm + mt * 16;
#pragma unroll
        for (int nt = 0; nt < 8; nt++) {
            const int col = n0 + wn + nt * 8 + ec;
            float v0 = acc[mt][nt][0], v1 = acc[mt][nt][1];
            float v2 = acc[mt][nt][2], v3 = acc[mt][nt][3];
            if (MODE == 0) {
                *reinterpret_cast<float2*>(C + (size_t)(rbase + er)     * Nglob + col) =
                    make_float2(v0, v1);
                *reinterpret_cast<float2*>(C + (size_t)(rbase + er + 8) * Nglob + col) =
                    make_float2(v2, v3);
            } else if (MODE == 1) {
                *reinterpret_cast<__half2*>(g_xih + (size_t)(rbase + er)     * DINNER + col) =
                    __floats2half2_rn(v0, v1);
                *reinterpret_cast<__half2*>(g_xih + (size_t)(rbase + er + 8) * DINNER + col) =
                    __floats2half2_rn(v2, v3);
            } else {
                v0 = v0 / (1.f + expf(-v0));
                v1 = v1 / (1.f + expf(-v1));
                v2 = v2 / (1.f + expf(-v2));
                v3 = v3 / (1.f + expf(-v3));
                *reinterpret_cast<__half2*>(g_resh + (size_t)(rbase + er)     * DINNER + col) =
                    __floats2half2_rn(v0, v1);
                *reinterpret_cast<__half2*>(g_resh + (size_t)(rbase + er + 8) * DINNER + col) =
                    __floats2half2_rn(v2, v3);
            }
        }
    }
}

// ============== small HMMA GEMM fused with dt/A_disc/Bu epilogue =============
#define SB_ROWB   2064
#define SB_BYTES  (32 * SB_ROWB)              // 66048
#define SA_TILE   (128 * LG_ROWB)             // 18432
#define GS_SMEM   (SB_BYTES + 2 * SA_TILE)    // 102912

__global__ __launch_bounds__(256, 1)
void gemm_small(const __half* __restrict__ A, const __half* __restrict__ B,
                const float* __restrict__ bdt, const float* __restrict__ Alog)
{
    extern __shared__ char smem[];
    const uint32_t sb = smem_to_u32(smem);
    const int tid  = threadIdx.x;
    const int wid  = tid >> 5;
    const int lane = tid & 31;
    const int m0 = blockIdx.x * 128;
    const int K = DINNER;
    const int nch = K / 64;

    {
#pragma unroll
        for (int i = 0; i < 16; i++) {
            int idx = tid + i * 256;
            int row = idx >> 7, cc = idx & 127;
            CP_ASYNC16(sb + (uint32_t)(row * SB_ROWB + cc * 16),
                       B + (size_t)row * K + cc * 8);
        }
        CP_COMMIT();
    }
    const uint32_t offA[2] = { (uint32_t)SB_BYTES, (uint32_t)(SB_BYTES + SA_TILE) };

    auto issueA = [&](int c, int b) {
        const __half* Ag = A + (size_t)m0 * K + (size_t)c * 64;
        const uint32_t sa = sb + offA[b];
#pragma unroll
        for (int i = 0; i < 4; i++) {
            int idx = tid + i * 256;
            int row = idx >> 3, cc = idx & 7;
            CP_ASYNC16(sa + (uint32_t)(row * LG_ROWB + cc * 16),
                       Ag + (size_t)row * K + cc * 8);
        }
        CP_COMMIT();
    };

    const int wm = wid * 16;
    float acc[4][4];
#pragma unroll
    for (int j = 0; j < 4; j++)
#pragma unroll
        for (int k = 0; k < 4; k++) acc[j][k] = 0.f;

    issueA(0, 0);
    for (int c = 0; c < nch; c++) {
        const int buf = c & 1;
        if (c + 1 < nch) { issueA(c + 1, buf ^ 1); CP_WAIT1(); }
        else             { CP_WAIT0(); }
        __syncthreads();

        const uint32_t aBase = sb + offA[buf];
        const int lrow = lane & 15;
        const int lcol = (lane >> 4) * 16;
#pragma unroll
        for (int ks = 0; ks < 4; ks++) {
            uint32_t af[4], bfr[2][4];
            LDSM_X4(af, aBase + (uint32_t)((wm + lrow) * LG_ROWB + ks*32 + lcol));
#pragma unroll
            for (int ng = 0; ng < 2; ng++)
                LDSM_X4(bfr[ng], sb + (uint32_t)((ng*16 + lrow) * SB_ROWB + (c*4 + ks)*32 + lcol));
#pragma unroll
            for (int nt = 0; nt < 4; nt++) {
                const int ng = nt >> 1, hi = nt & 1;
                MMA_F16(acc[nt], af, bfr[ng][hi], bfr[ng][2 + hi]);
            }
        }
        __syncthreads();
    }

    const int er = lane >> 2;
    const int ec = (lane & 3) * 2;
    const int r0 = m0 + wm + er;
    const float u0 = g_u[r0];
    const float u1 = g_u[r0 + 8];
#pragma unroll
    for (int nt = 0; nt < 2; nt++) {
#pragma unroll
        for (int j = 0; j < 2; j++) {
            const int n = nt * 8 + ec + j;
            const float A = -expf(Alog[n]);
            const float bn = bdt[n];
            {
                float raw = acc[nt][j] + bn;
                float dt  = raw > 20.f ? raw : log1pf(expf(raw));
                g_adisc[(size_t)r0 * DSTATE + n] = expf(A * dt);
                g_bu   [(size_t)r0 * DSTATE + n] = dt * acc[nt + 2][j] * u0;
            }
            {
                float raw = acc[nt][2 + j] + bn;
                float dt  = raw > 20.f ? raw : log1pf(expf(raw));
                g_adisc[(size_t)(r0 + 8) * DSTATE + n] = expf(A * dt);
                g_bu   [(size_t)(r0 + 8) * DSTATE + n] = dt * acc[nt + 2][2 + j] * u1;
            }
        }
    }
}

// ======================= fused prep (all fp32->fp16 conversions) =============
// blocks [0,1024): W_in -> g_wih      (1M elems)
// blocks [1024,1536): W_out -> g_woh  (512K)
// blocks [1536,9728): x -> g_xh       (8M)
// blocks [9728,9760): wcat -> g_wch   (32K)
#define PREP_BLOCKS 9760
__global__ void prep_kernel(const float* __restrict__ W_in, const float* __restrict__ W_out,
                            const float* __restrict__ x,
                            const float* __restrict__ Wx, const float* __restrict__ Wdt)
{
    const int b = blockIdx.x;
    if (b < 1024) {
        long i = ((long)b * 256 + threadIdx.x) * 4;
        float4 v = *reinterpret_cast<const float4*>(W_in + i);
        *reinterpret_cast<__half2*>(g_wih + i)     = __floats2half2_rn(v.x, v.y);
        *reinterpret_cast<__half2*>(g_wih + i + 2) = __floats2half2_rn(v.z, v.w);
    } else if (b < 1536) {
        long i = ((long)(b - 1024) * 256 + threadIdx.x) * 4;
        float4 v = *reinterpret_cast<const float4*>(W_out + i);
        *reinterpret_cast<__half2*>(g_woh + i)     = __floats2half2_rn(v.x, v.y);
        *reinterpret_cast<__half2*>(g_woh + i + 2) = __floats2half2_rn(v.z, v.w);
    } else if (b < 9728) {
        long i = ((long)(b - 1536) * 256 + threadIdx.x) * 4;
        float4 v = *reinterpret_cast<const float4*>(x + i);
        *reinterpret_cast<__half2*>(g_xh + i)     = __floats2half2_rn(v.x, v.y);
        *reinterpret_cast<__half2*>(g_xh + i + 2) = __floats2half2_rn(v.z, v.w);
    } else {
        int i = (b - 9728) * 1024 + threadIdx.x * 4;
        int row = i >> 10;
        const float* src = (row < DSTATE) ? Wdt : Wx;
        float4 v = *reinterpret_cast<const float4*>(src + i);
        *reinterpret_cast<__half2*>(g_wch + i)     = __floats2half2_rn(v.x, v.y);
        *reinterpret_cast<__half2*>(g_wch + i + 2) = __floats2half2_rn(v.z, v.w);
    }
}

// ======================= conv(4)+bias+SiLU + fused u =========================
__global__ void conv_silu_kernel(const float* __restrict__ cw, const float* __restrict__ cb)
{
    const int m  = blockIdx.x;
    const int c4 = threadIdx.x;
    const int c  = c4 * 4;
    const int l  = m & (SEQLEN - 1);

    float w[4][4];
#pragma unroll
    for (int j = 0; j < 4; j++)
        *reinterpret_cast<float4*>(w[j]) =
            *reinterpret_cast<const float4*>(cw + (size_t)(c + j) * DCONV);
    float4 b = *reinterpret_cast<const float4*>(cb + c);
    float a0 = b.x, a1 = b.y, a2 = b.z, a3 = b.w;
#pragma unroll
    for (int t = 0; t < DCONV; t++) {
        int ls = l - (DCONV - 1) + t;
        if (ls >= 0) {
            const __half* xp = g_xih + (size_t)(m - (DCONV - 1) + t) * DINNER + c;
            float2 f0 = __half22float2(*reinterpret_cast<const __half2*>(xp));
            float2 f1 = __half22float2(*reinterpret_cast<const __half2*>(xp + 2));
            a0 = fmaf(w[0][t], f0.x, a0);
            a1 = fmaf(w[1][t], f0.y, a1);
            a2 = fmaf(w[2][t], f1.x, a2);
            a3 = fmaf(w[3][t], f1.y, a3);
        }
    }
    float o0 = a0 / (1.f + expf(-a0));
    float o1 = a1 / (1.f + expf(-a1));
    float o2 = a2 / (1.f + expf(-a2));
    float o3 = a3 / (1.f + expf(-a3));
    __half* hp = g_xah + (size_t)m * DINNER + c;
    *reinterpret_cast<__half2*>(hp)     = __floats2half2_rn(o0, o1);
    *reinterpret_cast<__half2*>(hp + 2) = __floats2half2_rn(o2, o3);

    if (c4 < 16) {
        float s = o0 + o1 + o2 + o3;
#pragma unroll
        for (int o = 8; o; o >>= 1) s += __shfl_down_sync(0xffffu, s, o);
        if (c4 == 0) g_u[m] = s * (1.f / 64.f);
    }
}

// ======================= fused 3-phase scan (grid=BATCH, block=512) ==========
__global__ void scan_kernel()
{
    __shared__ float sA[NCHUNK][DSTATE];
    __shared__ float sV[NCHUNK][DSTATE];
    __shared__ float sC[NCHUNK][DSTATE];
    const int b = blockIdx.x;
    const int tid = threadIdx.x;        // 512 = 32 chunks x 16 states
    const int c = tid >> 4;
    const int n = tid & 15;
    const size_t base = ((size_t)b * SEQLEN + (size_t)c * SCHUNK) * DSTATE + n;

    float A = 1.f, V = 0.f;
#pragma unroll 8
    for (int i = 0; i < SCHUNK; i++) {
        float a = g_adisc[base + (size_t)i * DSTATE];
        float v = g_bu   [base + (size_t)i * DSTATE];
        V = fmaf(a, V, v);
        A *= a;
    }
    sA[c][n] = A; sV[c][n] = V;
    __syncthreads();
    if (tid < DSTATE) {
        float s = 0.f;
#pragma unroll
        for (int cc = 0; cc < NCHUNK; cc++) {
            sC[cc][tid] = s;
            s = fmaf(sA[cc][tid], s, sV[cc][tid]);
        }
    }
    __syncthreads();
    float s = sC[c][n];
#pragma unroll 8
    for (int i = 0; i < SCHUNK; i++) {
        float a = g_adisc[base + (size_t)i * DSTATE];
        float v = g_bu   [base + (size_t)i * DSTATE];
        s = fmaf(a, s, v);
        g_y[base + (size_t)i * DSTATE] = s;
    }
}

// ======================= gate + skip -> fp16 y_full ===========================
__global__ void elt_kernel(const float* __restrict__ Dp)
{
    int idx = blockIdx.x * blockDim.x + threadIdx.x;
    int c4 = idx & (DINNER/4 - 1);
    int m  = idx >> 8;
    int c  = c4 * 4;
    float yv  = g_y[(size_t)m * DSTATE + (c >> 6)];
    const __half* xp = g_xah + (size_t)m * DINNER + c;
    float2 x0 = __half22float2(*reinterpret_cast<const __half2*>(xp));
    float2 x1 = __half22float2(*reinterpret_cast<const __half2*>(xp + 2));
    float4 D  = *reinterpret_cast<const float4*>(Dp + c);
    const __half* rp = g_resh + (size_t)m * DINNER + c;
    float2 r0 = __half22float2(*reinterpret_cast<const __half2*>(rp));
    float2 r1 = __half22float2(*reinterpret_cast<const __half2*>(rp + 2));
    float o0 = (yv + x0.x * D.x) * r0.x;
    float o1 = (yv + x0.y * D.y) * r0.y;
    float o2 = (yv + x1.x * D.z) * r1.x;
    float o3 = (yv + x1.y * D.w) * r1.y;
    __half* row = g_yh + (size_t)m * DINNER + c;
    *reinterpret_cast<__half2*>(row)     = __floats2half2_rn(o0, o1);
    *reinterpret_cast<__half2*>(row + 2) = __floats2half2_rn(o2, o3);
}

// ======================= launch ==============================================
extern "C" void kernel_launch(void* const* d_in, const int* in_sizes, int n_in,
                              void* d_out, int out_size)
{
    const float* x      = (const float*)d_in[0];
    const float* W_in   = (const float*)d_in[1];
    const float* conv_w = (const float*)d_in[2];
    const float* conv_b = (const float*)d_in[3];
    const float* W_x    = (const float*)d_in[4];
    const float* W_dt   = (const float*)d_in[5];
    const float* b_dt   = (const float*)d_in[6];
    const float* A_log  = (const float*)d_in[7];
    const float* D_par  = (const float*)d_in[8];
    const float* W_out  = (const float*)d_in[9];
    float* out = (float*)d_out;

    __half* xh;  cudaGetSymbolAddress((void**)&xh,  g_xh);
    __half* xah; cudaGetSymbolAddress((void**)&xah, g_xah);
    __half* yh;  cudaGetSymbolAddress((void**)&yh,  g_yh);
    __half* wih; cudaGetSymbolAddress((void**)&wih, g_wih);
    __half* woh; cudaGetSymbolAddress((void**)&woh, g_woh);
    __half* wch; cudaGetSymbolAddress((void**)&wch, g_wch);

    cudaFuncSetAttribute(gemm_hmma<0>, cudaFuncAttributeMaxDynamicSharedMemorySize, GH_SMEM);
    cudaFuncSetAttribute(gemm_hmma<1>, cudaFuncAttributeMaxDynamicSharedMemorySize, GH_SMEM);
    cudaFuncSetAttribute(gemm_hmma<2>, cudaFuncAttributeMaxDynamicSharedMemorySize, GH_SMEM);
    cudaFuncSetAttribute(gemm_small,   cudaFuncAttributeMaxDynamicSharedMemorySize, GS_SMEM);

    // side stream + events for the res-half overlap (created fresh each call;
    // intentionally not destroyed to avoid touching objects referenced by an
    // in-progress capture — host-side only, a few objects per call)
    cudaStream_t s2;
    cudaStreamCreateWithFlags(&s2, cudaStreamNonBlocking);
    cudaEvent_t evA, evB;
    cudaEventCreateWithFlags(&evA, cudaEventDisableTiming);
    cudaEventCreateWithFlags(&evB, cudaEventDisableTiming);

    // 0. all fp32->fp16 prep in one kernel
    prep_kernel<<<PREP_BLOCKS, 256>>>(W_in, W_out, x, W_x, W_dt);

    // 1a. GEMM1 xi half (W_in rows 0..1023) -> g_xih
    gemm_hmma<1><<<dim3(DINNER/128, M_TOK/128), 256, GH_SMEM>>>(
        xh, wih, nullptr, 0, DIM);

    // fork: res half on side stream (W_in rows 1024..2047) -> silu -> g_resh
    cudaEventRecord(evA, 0);
    cudaStreamWaitEvent(s2, evA, 0);
    gemm_hmma<2><<<dim3(DINNER/128, M_TOK/128), 256, GH_SMEM, s2>>>(
        xh, wih + (size_t)DINNER * DIM, nullptr, 0, DIM);
    cudaEventRecord(evB, s2);

    // 1b. dependent chain on main stream (overlaps with res half)
    conv_silu_kernel<<<M_TOK, 256>>>(conv_w, conv_b);
    gemm_small<<<M_TOK/128, 256, GS_SMEM>>>(xah, wch, b_dt, A_log);
    scan_kernel<<<BATCH, 512>>>();

    // join: elt needs g_resh
    cudaStreamWaitEvent(0, evB, 0);
    elt_kernel<<<(M_TOK*(DINNER/4))/256, 256>>>(D_par);

    // 2. GEMM2
    gemm_hmma<0><<<dim3(DIM/128, M_TOK/128), 256, GH_SMEM>>>(
        yh, woh, out, DIM, DINNER);
}

// round 13
// speedup vs baseline: 1.6001x; 1.1012x over previous
#include <cuda_runtime.h>
#include <cuda_fp16.h>
#include <math.h>
#include <stdint.h>

#define BATCH   4
#define SEQLEN  4096
#define DIM     512
#define DINNER  1024
#define DSTATE  16
#define DCONV   4
#define M_TOK   (BATCH*SEQLEN)   // 16384

// ======================= PTX helpers (sm_80 baseline) ========================
__device__ __forceinline__ uint32_t smem_to_u32(const void* p) {
    uint32_t a;
    asm("{ .reg .u64 t; cvta.to.shared.u64 t, %1; cvt.u32.u64 %0, t; }"
        : "=r"(a) : "l"(p));
    return a;
}
#define CP_ASYNC16(saddr, gptr) \
    asm volatile("cp.async.cg.shared.global [%0], [%1], 16;" \
        :: "r"(saddr), "l"(gptr))
#define CP_COMMIT() asm volatile("cp.async.commit_group;" ::: "memory")
#define CP_WAIT1()  asm volatile("cp.async.wait_group 1;" ::: "memory")
#define CP_WAIT0()  asm volatile("cp.async.wait_group 0;" ::: "memory")

#define LDSM_X4(r, addr) \
    asm volatile("ldmatrix.sync.aligned.m8n8.x4.shared.b16 {%0,%1,%2,%3}, [%4];" \
        : "=r"((r)[0]), "=r"((r)[1]), "=r"((r)[2]), "=r"((r)[3]) : "r"(addr))

#define MMA_F16(d, a, b0, b1) \
    asm volatile("mma.sync.aligned.m16n8k16.row.col.f32.f16.f16.f32 " \
        "{%0,%1,%2,%3}, {%4,%5,%6,%7}, {%8,%9}, {%0,%1,%2,%3};" \
        : "+f"((d)[0]), "+f"((d)[1]), "+f"((d)[2]), "+f"((d)[3]) \
        : "r"((a)[0]), "r"((a)[1]), "r"((a)[2]), "r"((a)[3]), "r"(b0), "r"(b1))

// ======================= scratch =============================================
__device__ __align__(256) float  g_u   [M_TOK];
__device__ __align__(256) float  g_adisc[(size_t)M_TOK * DSTATE];
__device__ __align__(256) float  g_bu  [(size_t)M_TOK * DSTATE];
__device__ __align__(256) float  g_y   [(size_t)M_TOK * DSTATE];
// fp16 planes
__device__ __align__(256) __half g_xh  [(size_t)M_TOK * DIM];
__device__ __align__(256) __half g_xih [(size_t)M_TOK * DINNER];
__device__ __align__(256) __half g_resh[(size_t)M_TOK * DINNER];
__device__ __align__(256) __half g_xah [(size_t)M_TOK * DINNER];
__device__ __align__(256) __half g_yh  [(size_t)M_TOK * DINNER];
__device__ __align__(256) __half g_wih [(size_t)2*DINNER * DIM];
__device__ __align__(256) __half g_woh [(size_t)DIM * DINNER];
__device__ __align__(256) __half g_wch [2 * DSTATE * DINNER];
// scan constants
#define SCHUNK  128
#define NCHUNK  (SEQLEN / SCHUNK)   // 32

// ======================= HMMA fp16 GEMM ======================================
// Block tile 128x128, 256 threads (8 warps 4x2, warp tile 32x64),
// K-chunk 64, cp.async double buffer. m_off shifts the M origin (tail split).
// MODE 0: fp32 C (Nglob stride). MODE 1: write g_xih. MODE 2: silu -> g_resh.
#define LG_ROWB   144
#define LG_TILE_B (128 * LG_ROWB)          // 18432 B
#define GH_SMEM   (4 * LG_TILE_B)          // 73728 B

template<int MODE>
__global__ __launch_bounds__(256, 2)
void gemm_hmma(const __half* __restrict__ A, const __half* __restrict__ B,
               float* __restrict__ C, int Nglob, int K, int m_off)
{
    extern __shared__ char smem[];
    const uint32_t sb = smem_to_u32(smem);
    const int tid  = threadIdx.x;
    const int wid  = tid >> 5;
    const int lane = tid & 31;
    const int m0 = m_off + blockIdx.y * 128;
    const int n0 = blockIdx.x * 128;
    const int nch = K / 64;

    const int wm = (wid & 3) * 32;
    const int wn = (wid >> 2) * 64;
    const uint32_t offA[2] = { 0u,              2u * LG_TILE_B };
    const uint32_t offB[2] = { (uint32_t)LG_TILE_B, 3u * LG_TILE_B };

    float acc[2][8][4];
#pragma unroll
    for (int i = 0; i < 2; i++)
#pragma unroll
        for (int j = 0; j < 8; j++)
#pragma unroll
            for (int k = 0; k < 4; k++) acc[i][j][k] = 0.f;

    auto issue = [&](int c, int b) {
        const __half* Ag = A + (size_t)m0 * K + (size_t)c * 64;
        const __half* Bg = B + (size_t)n0 * K + (size_t)c * 64;
        const uint32_t sa  = sb + offA[b];
        const uint32_t sbm = sb + offB[b];
#pragma unroll
        for (int i = 0; i < 4; i++) {
            int idx = tid + i * 256;
            int row = idx >> 3, cc = idx & 7;
            CP_ASYNC16(sa  + (uint32_t)(row * LG_ROWB + cc * 16),
                       Ag + (size_t)row * K + cc * 8);
            CP_ASYNC16(sbm + (uint32_t)(row * LG_ROWB + cc * 16),
                       Bg + (size_t)row * K + cc * 8);
        }
        CP_COMMIT();
    };

    issue(0, 0);
    for (int c = 0; c < nch; c++) {
        const int buf = c & 1;
        if (c + 1 < nch) { issue(c + 1, buf ^ 1); CP_WAIT1(); }
        else             { CP_WAIT0(); }
        __syncthreads();

        const uint32_t aBase = sb + offA[buf];
        const uint32_t bBase = sb + offB[buf];
        const int lrow = lane & 15;
        const int lcol = (lane >> 4) * 16;
#pragma unroll
        for (int ks = 0; ks < 4; ks++) {
            uint32_t af[2][4], bfr[4][4];
#pragma unroll
            for (int mt = 0; mt < 2; mt++)
                LDSM_X4(af[mt], aBase + (uint32_t)((wm + mt*16 + lrow) * LG_ROWB + ks*32 + lcol));
#pragma unroll
            for (int ng = 0; ng < 4; ng++)
                LDSM_X4(bfr[ng], bBase + (uint32_t)((wn + ng*16 + lrow) * LG_ROWB + ks*32 + lcol));
#pragma unroll
            for (int mt = 0; mt < 2; mt++)
#pragma unroll
                for (int nt = 0; nt < 8; nt++) {
                    const int ng = nt >> 1, hi = nt & 1;
                    MMA_F16(acc[mt][nt], af[mt], bfr[ng][hi], bfr[ng][2 + hi]);
                }
        }
        __syncthreads();
    }

    const int er = lane >> 2;
    const int ec = (lane & 3) * 2;
#pragma unroll
    for (int mt = 0; mt < 2; mt++) {
        const int rbase = m0 + wm + mt * 16;
#pragma unroll
        for (int nt = 0; nt < 8; nt++) {
            const int col = n0 + wn + nt * 8 + ec;
            float v0 = acc[mt][nt][0], v1 = acc[mt][nt][1];
            float v2 = acc[mt][nt][2], v3 = acc[mt][nt][3];
            if (MODE == 0) {
                *reinterpret_cast<float2*>(C + (size_t)(rbase + er)     * Nglob + col) =
                    make_float2(v0, v1);
                *reinterpret_cast<float2*>(C + (size_t)(rbase + er + 8) * Nglob + col) =
                    make_float2(v2, v3);
            } else if (MODE == 1) {
                *reinterpret_cast<__half2*>(g_xih + (size_t)(rbase + er)     * DINNER + col) =
                    __floats2half2_rn(v0, v1);
                *reinterpret_cast<__half2*>(g_xih + (size_t)(rbase + er + 8) * DINNER + col) =
                    __floats2half2_rn(v2, v3);
            } else {
                v0 = v0 / (1.f + expf(-v0));
                v1 = v1 / (1.f + expf(-v1));
                v2 = v2 / (1.f + expf(-v2));
                v3 = v3 / (1.f + expf(-v3));
                *reinterpret_cast<__half2*>(g_resh + (size_t)(rbase + er)     * DINNER + col) =
                    __floats2half2_rn(v0, v1);
                *reinterpret_cast<__half2*>(g_resh + (size_t)(rbase + er + 8) * DINNER + col) =
                    __floats2half2_rn(v2, v3);
            }
        }
    }
}

// ============== small HMMA GEMM fused with dt/A_disc/Bu epilogue =============
#define SB_ROWB   2064
#define SB_BYTES  (32 * SB_ROWB)              // 66048
#define SA_TILE   (128 * LG_ROWB)             // 18432
#define GS_SMEM   (SB_BYTES + 2 * SA_TILE)    // 102912

__global__ __launch_bounds__(256, 1)
void gemm_small(const __half* __restrict__ A, const __half* __restrict__ B,
                const float* __restrict__ bdt, const float* __restrict__ Alog)
{
    extern __shared__ char smem[];
    const uint32_t sb = smem_to_u32(smem);
    const int tid  = threadIdx.x;
    const int wid  = tid >> 5;
    const int lane = tid & 31;
    const int m0 = blockIdx.x * 128;
    const int K = DINNER;
    const int nch = K / 64;

    {
#pragma unroll
        for (int i = 0; i < 16; i++) {
            int idx = tid + i * 256;
            int row = idx >> 7, cc = idx & 127;
            CP_ASYNC16(sb + (uint32_t)(row * SB_ROWB + cc * 16),
                       B + (size_t)row * K + cc * 8);
        }
        CP_COMMIT();
    }
    const uint32_t offA[2] = { (uint32_t)SB_BYTES, (uint32_t)(SB_BYTES + SA_TILE) };

    auto issueA = [&](int c, int b) {
        const __half* Ag = A + (size_t)m0 * K + (size_t)c * 64;
        const uint32_t sa = sb + offA[b];
#pragma unroll
        for (int i = 0; i < 4; i++) {
            int idx = tid + i * 256;
            int row = idx >> 3, cc = idx & 7;
            CP_ASYNC16(sa + (uint32_t)(row * LG_ROWB + cc * 16),
                       Ag + (size_t)row * K + cc * 8);
        }
        CP_COMMIT();
    };

    const int wm = wid * 16;
    float acc[4][4];
#pragma unroll
    for (int j = 0; j < 4; j++)
#pragma unroll
        for (int k = 0; k < 4; k++) acc[j][k] = 0.f;

    issueA(0, 0);
    for (int c = 0; c < nch; c++) {
        const int buf = c & 1;
        if (c + 1 < nch) { issueA(c + 1, buf ^ 1); CP_WAIT1(); }
        else             { CP_WAIT0(); }
        __syncthreads();

        const uint32_t aBase = sb + offA[buf];
        const int lrow = lane & 15;
        const int lcol = (lane >> 4) * 16;
#pragma unroll
        for (int ks = 0; ks < 4; ks++) {
            uint32_t af[4], bfr[2][4];
            LDSM_X4(af, aBase + (uint32_t)((wm + lrow) * LG_ROWB + ks*32 + lcol));
#pragma unroll
            for (int ng = 0; ng < 2; ng++)
                LDSM_X4(bfr[ng], sb + (uint32_t)((ng*16 + lrow) * SB_ROWB + (c*4 + ks)*32 + lcol));
#pragma unroll
            for (int nt = 0; nt < 4; nt++) {
                const int ng = nt >> 1, hi = nt & 1;
                MMA_F16(acc[nt], af, bfr[ng][hi], bfr[ng][2 + hi]);
            }
        }
        __syncthreads();
    }

    const int er = lane >> 2;
    const int ec = (lane & 3) * 2;
    const int r0 = m0 + wm + er;
    const float u0 = g_u[r0];
    const float u1 = g_u[r0 + 8];
#pragma unroll
    for (int nt = 0; nt < 2; nt++) {
#pragma unroll
        for (int j = 0; j < 2; j++) {
            const int n = nt * 8 + ec + j;
            const float A = -expf(Alog[n]);
            const float bn = bdt[n];
            {
                float raw = acc[nt][j] + bn;
                float dt  = raw > 20.f ? raw : log1pf(expf(raw));
                g_adisc[(size_t)r0 * DSTATE + n] = expf(A * dt);
                g_bu   [(size_t)r0 * DSTATE + n] = dt * acc[nt + 2][j] * u0;
            }
            {
                float raw = acc[nt][2 + j] + bn;
                float dt  = raw > 20.f ? raw : log1pf(expf(raw));
                g_adisc[(size_t)(r0 + 8) * DSTATE + n] = expf(A * dt);
                g_bu   [(size_t)(r0 + 8) * DSTATE + n] = dt * acc[nt + 2][2 + j] * u1;
            }
        }
    }
}

// ======================= prep kernels ========================================
// prep_x: x -> g_xh (8192 blocks). prep_w: wih/woh/wch (1568 blocks).
__global__ void prep_x_kernel(const float* __restrict__ x)
{
    long i = ((long)blockIdx.x * 256 + threadIdx.x) * 4;
    float4 v = *reinterpret_cast<const float4*>(x + i);
    *reinterpret_cast<__half2*>(g_xh + i)     = __floats2half2_rn(v.x, v.y);
    *reinterpret_cast<__half2*>(g_xh + i + 2) = __floats2half2_rn(v.z, v.w);
}
__global__ void prep_w_kernel(const float* __restrict__ W_in, const float* __restrict__ W_out,
                              const float* __restrict__ Wx, const float* __restrict__ Wdt)
{
    const int b = blockIdx.x;
    if (b < 1024) {
        long i = ((long)b * 256 + threadIdx.x) * 4;
        float4 v = *reinterpret_cast<const float4*>(W_in + i);
        *reinterpret_cast<__half2*>(g_wih + i)     = __floats2half2_rn(v.x, v.y);
        *reinterpret_cast<__half2*>(g_wih + i + 2) = __floats2half2_rn(v.z, v.w);
    } else if (b < 1536) {
        long i = ((long)(b - 1024) * 256 + threadIdx.x) * 4;
        float4 v = *reinterpret_cast<const float4*>(W_out + i);
        *reinterpret_cast<__half2*>(g_woh + i)     = __floats2half2_rn(v.x, v.y);
        *reinterpret_cast<__half2*>(g_woh + i + 2) = __floats2half2_rn(v.z, v.w);
    } else {
        int i = (b - 1536) * 1024 + threadIdx.x * 4;
        int row = i >> 10;
        const float* src = (row < DSTATE) ? Wdt : Wx;
        float4 v = *reinterpret_cast<const float4*>(src + i);
        *reinterpret_cast<__half2*>(g_wch + i)     = __floats2half2_rn(v.x, v.y);
        *reinterpret_cast<__half2*>(g_wch + i + 2) = __floats2half2_rn(v.z, v.w);
    }
}

// ======================= conv: rolling window, coalesced =====================
// block = 256 threads (all channel quads), CONV_T consecutive tokens.
// Each xih row read once (vs 4x before); u fused (channels 0..63 = c4 0..15).
#define CONV_T 32
__global__ __launch_bounds__(256)
void conv_silu_kernel(const float* __restrict__ cw, const float* __restrict__ cb)
{
    const int c4 = threadIdx.x;
    const int c  = c4 * 4;
    const int t0 = blockIdx.x * CONV_T;
    const int l0 = t0 & (SEQLEN - 1);

    float w[4][4];
#pragma unroll
    for (int j = 0; j < 4; j++)
        *reinterpret_cast<float4*>(w[j]) =
            *reinterpret_cast<const float4*>(cw + (size_t)(c + j) * DCONV);
    const float4 bias = *reinterpret_cast<const float4*>(cb + c);

    auto loadrow = [&](int t) -> float4 {
        const __half* xp = g_xih + (size_t)t * DINNER + c;
        float2 f0 = __half22float2(*reinterpret_cast<const __half2*>(xp));
        float2 f1 = __half22float2(*reinterpret_cast<const __half2*>(xp + 2));
        return make_float4(f0.x, f0.y, f1.x, f1.y);
    };

    float4 h0, h1, h2;
    if (l0 != 0) {                      // blocks are 32-token aligned: l0==0 is seq start
        h0 = loadrow(t0 - 3); h1 = loadrow(t0 - 2); h2 = loadrow(t0 - 1);
    } else {
        h0 = make_float4(0.f, 0.f, 0.f, 0.f); h1 = h0; h2 = h0;
    }
    float4 cur = loadrow(t0);

#pragma unroll 4
    for (int i = 0; i < CONV_T; i++) {
        float4 nxt = make_float4(0.f, 0.f, 0.f, 0.f);
        if (i + 1 < CONV_T) nxt = loadrow(t0 + i + 1);

        float a0 = bias.x, a1 = bias.y, a2 = bias.z, a3 = bias.w;
        a0 = fmaf(w[0][0], h0.x, a0); a0 = fmaf(w[0][1], h1.x, a0);
        a0 = fmaf(w[0][2], h2.x, a0); a0 = fmaf(w[0][3], cur.x, a0);
        a1 = fmaf(w[1][0], h0.y, a1); a1 = fmaf(w[1][1], h1.y, a1);
        a1 = fmaf(w[1][2], h2.y, a1); a1 = fmaf(w[1][3], cur.y, a1);
        a2 = fmaf(w[2][0], h0.z, a2); a2 = fmaf(w[2][1], h1.z, a2);
        a2 = fmaf(w[2][2], h2.z, a2); a2 = fmaf(w[2][3], cur.z, a2);
        a3 = fmaf(w[3][0], h0.w, a3); a3 = fmaf(w[3][1], h1.w, a3);
        a3 = fmaf(w[3][2], h2.w, a3); a3 = fmaf(w[3][3], cur.w, a3);

        float o0 = a0 / (1.f + expf(-a0));
        float o1 = a1 / (1.f + expf(-a1));
        float o2 = a2 / (1.f + expf(-a2));
        float o3 = a3 / (1.f + expf(-a3));

        __half* hp = g_xah + (size_t)(t0 + i) * DINNER + c;
        *reinterpret_cast<__half2*>(hp)     = __floats2half2_rn(o0, o1);
        *reinterpret_cast<__half2*>(hp + 2) = __floats2half2_rn(o2, o3);

        if (c4 < 16) {
            float s = o0 + o1 + o2 + o3;
#pragma unroll
            for (int o = 8; o; o >>= 1) s += __shfl_down_sync(0xffffu, s, o);
            if (c4 == 0) g_u[t0 + i] = s * (1.f / 64.f);
        }
        h0 = h1; h1 = h2; h2 = cur; cur = nxt;
    }
}

// ======================= fused 3-phase scan (grid=BATCH, block=512) ==========
__global__ void scan_kernel()
{
    __shared__ float sA[NCHUNK][DSTATE];
    __shared__ float sV[NCHUNK][DSTATE];
    __shared__ float sC[NCHUNK][DSTATE];
    const int b = blockIdx.x;
    const int tid = threadIdx.x;
    const int c = tid >> 4;
    const int n = tid & 15;
    const size_t base = ((size_t)b * SEQLEN + (size_t)c * SCHUNK) * DSTATE + n;

    float A = 1.f, V = 0.f;
#pragma unroll 8
    for (int i = 0; i < SCHUNK; i++) {
        float a = g_adisc[base + (size_t)i * DSTATE];
        float v = g_bu   [base + (size_t)i * DSTATE];
        V = fmaf(a, V, v);
        A *= a;
    }
    sA[c][n] = A; sV[c][n] = V;
    __syncthreads();
    if (tid < DSTATE) {
        float s = 0.f;
#pragma unroll
        for (int cc = 0; cc < NCHUNK; cc++) {
            sC[cc][tid] = s;
            s = fmaf(sA[cc][tid], s, sV[cc][tid]);
        }
    }
    __syncthreads();
    float s = sC[c][n];
#pragma unroll 8
    for (int i = 0; i < SCHUNK; i++) {
        float a = g_adisc[base + (size_t)i * DSTATE];
        float v = g_bu   [base + (size_t)i * DSTATE];
        s = fmaf(a, s, v);
        g_y[base + (size_t)i * DSTATE] = s;
    }
}

// ======================= gate + skip -> fp16 y_full ===========================
__global__ void elt_kernel(const float* __restrict__ Dp, int m_off)
{
    int idx = blockIdx.x * blockDim.x + threadIdx.x;
    int c4 = idx & (DINNER/4 - 1);
    int m  = m_off + (idx >> 8);
    int c  = c4 * 4;
    float yv  = g_y[(size_t)m * DSTATE + (c >> 6)];
    const __half* xp = g_xah + (size_t)m * DINNER + c;
    float2 x0 = __half22float2(*reinterpret_cast<const __half2*>(xp));
    float2 x1 = __half22float2(*reinterpret_cast<const __half2*>(xp + 2));
    float4 D  = *reinterpret_cast<const float4*>(Dp + c);
    const __half* rp = g_resh + (size_t)m * DINNER + c;
    float2 r0 = __half22float2(*reinterpret_cast<const __half2*>(rp));
    float2 r1 = __half22float2(*reinterpret_cast<const __half2*>(rp + 2));
    float o0 = (yv + x0.x * D.x) * r0.x;
    float o1 = (yv + x0.y * D.y) * r0.y;
    float o2 = (yv + x1.x * D.z) * r1.x;
    float o3 = (yv + x1.y * D.w) * r1.y;
    __half* row = g_yh + (size_t)m * DINNER + c;
    *reinterpret_cast<__half2*>(row)     = __floats2half2_rn(o0, o1);
    *reinterpret_cast<__half2*>(row + 2) = __floats2half2_rn(o2, o3);
}

// ======================= launch ==============================================
extern "C" void kernel_launch(void* const* d_in, const int* in_sizes, int n_in,
                              void* d_out, int out_size)
{
    const float* x      = (const float*)d_in[0];
    const float* W_in   = (const float*)d_in[1];
    const float* conv_w = (const float*)d_in[2];
    const float* conv_b = (const float*)d_in[3];
    const float* W_x    = (const float*)d_in[4];
    const float* W_dt   = (const float*)d_in[5];
    const float* b_dt   = (const float*)d_in[6];
    const float* A_log  = (const float*)d_in[7];
    const float* D_par  = (const float*)d_in[8];
    const float* W_out  = (const float*)d_in[9];
    float* out = (float*)d_out;

    __half* xh;  cudaGetSymbolAddress((void**)&xh,  g_xh);
    __half* xah; cudaGetSymbolAddress((void**)&xah, g_xah);
    __half* yh;  cudaGetSymbolAddress((void**)&yh,  g_yh);
    __half* wih; cudaGetSymbolAddress((void**)&wih, g_wih);
    __half* woh; cudaGetSymbolAddress((void**)&woh, g_woh);
    __half* wch; cudaGetSymbolAddress((void**)&wch, g_wch);

    cudaFuncSetAttribute(gemm_hmma<0>, cudaFuncAttributeMaxDynamicSharedMemorySize, GH_SMEM);
    cudaFuncSetAttribute(gemm_hmma<1>, cudaFuncAttributeMaxDynamicSharedMemorySize, GH_SMEM);
    cudaFuncSetAttribute(gemm_hmma<2>, cudaFuncAttributeMaxDynamicSharedMemorySize, GH_SMEM);
    cudaFuncSetAttribute(gemm_small,   cudaFuncAttributeMaxDynamicSharedMemorySize, GS_SMEM);

    cudaStream_t s2;
    cudaStreamCreateWithFlags(&s2, cudaStreamNonBlocking);
    cudaEvent_t ev0, evW, evA, evB, evScan, evE1;
    cudaEventCreateWithFlags(&ev0,    cudaEventDisableTiming);
    cudaEventCreateWithFlags(&evW,    cudaEventDisableTiming);
    cudaEventCreateWithFlags(&evA,    cudaEventDisableTiming);
    cudaEventCreateWithFlags(&evB,    cudaEventDisableTiming);
    cudaEventCreateWithFlags(&evScan, cudaEventDisableTiming);
    cudaEventCreateWithFlags(&evE1,   cudaEventDisableTiming);

    // fork s2 from capture origin, weight conversions on s2
    cudaEventRecord(ev0, 0);
    cudaStreamWaitEvent(s2, ev0, 0);
    prep_w_kernel<<<1568, 256, 0, s2>>>(W_in, W_out, W_x, W_dt);
    cudaEventRecord(evW, s2);

    // x conversion on main
    prep_x_kernel<<<(M_TOK*DIM)/1024, 256>>>(x);
    cudaStreamWaitEvent(0, evW, 0);

    // GEMM1a: xi half -> g_xih
    gemm_hmma<1><<<dim3(DINNER/128, M_TOK/128), 256, GH_SMEM>>>(
        xh, wih, nullptr, 0, DIM, 0);

    // fork: GEMM1b res half on s2 (silu -> g_resh)
    cudaEventRecord(evA, 0);
    cudaStreamWaitEvent(s2, evA, 0);
    gemm_hmma<2><<<dim3(DINNER/128, M_TOK/128), 256, GH_SMEM, s2>>>(
        xh, wih + (size_t)DINNER * DIM, nullptr, 0, DIM, 0);
    cudaEventRecord(evB, s2);

    // dependent chain on main (overlaps GEMM1b)
    conv_silu_kernel<<<M_TOK/CONV_T, 256>>>(conv_w, conv_b);
    gemm_small<<<M_TOK/128, 256, GS_SMEM>>>(xah, wch, b_dt, A_log);
    scan_kernel<<<BATCH, 512>>>();
    cudaEventRecord(evScan, 0);

    // tail split: elt_h0 on main; elt_h1 on s2 (after scan + G1b)
    cudaStreamWaitEvent(0, evB, 0);
    elt_kernel<<<(M_TOK/2)*(DINNER/4)/256, 256>>>(D_par, 0);
    cudaStreamWaitEvent(s2, evScan, 0);
    elt_kernel<<<(M_TOK/2)*(DINNER/4)/256, 256, 0, s2>>>(D_par, M_TOK/2);
    cudaEventRecord(evE1, s2);

    // GEMM2 halves: h0 overlaps elt_h1
    gemm_hmma<0><<<dim3(DIM/128, M_TOK/256), 256, GH_SMEM>>>(
        yh, woh, out, DIM, DINNER, 0);
    cudaStreamWaitEvent(0, evE1, 0);
    gemm_hmma<0><<<dim3(DIM/128, M_TOK/256), 256, GH_SMEM>>>(
        yh, woh, out, DIM, DINNER, M_TOK/2);
}

// round 14
// speedup vs baseline: 1.7036x; 1.0647x over previous
#include <cuda_runtime.h>
#include <cuda_fp16.h>
#include <math.h>
#include <stdint.h>

#define BATCH   4
#define SEQLEN  4096
#define DIM     512
#define DINNER  1024
#define DSTATE  16
#define DCONV   4
#define M_TOK   (BATCH*SEQLEN)   // 16384

// ======================= PTX helpers (sm_80 baseline) ========================
__device__ __forceinline__ uint32_t smem_to_u32(const void* p) {
    uint32_t a;
    asm("{ .reg .u64 t; cvta.to.shared.u64 t, %1; cvt.u32.u64 %0, t; }"
        : "=r"(a) : "l"(p));
    return a;
}
#define CP_ASYNC16(saddr, gptr) \
    asm volatile("cp.async.cg.shared.global [%0], [%1], 16;" \
        :: "r"(saddr), "l"(gptr))
#define CP_COMMIT() asm volatile("cp.async.commit_group;" ::: "memory")
#define CP_WAIT1()  asm volatile("cp.async.wait_group 1;" ::: "memory")
#define CP_WAIT0()  asm volatile("cp.async.wait_group 0;" ::: "memory")

#define LDSM_X4(r, addr) \
    asm volatile("ldmatrix.sync.aligned.m8n8.x4.shared.b16 {%0,%1,%2,%3}, [%4];" \
        : "=r"((r)[0]), "=r"((r)[1]), "=r"((r)[2]), "=r"((r)[3]) : "r"(addr))

#define MMA_F16(d, a, b0, b1) \
    asm volatile("mma.sync.aligned.m16n8k16.row.col.f32.f16.f16.f32 " \
        "{%0,%1,%2,%3}, {%4,%5,%6,%7}, {%8,%9}, {%0,%1,%2,%3};" \
        : "+f"((d)[0]), "+f"((d)[1]), "+f"((d)[2]), "+f"((d)[3]) \
        : "r"((a)[0]), "r"((a)[1]), "r"((a)[2]), "r"((a)[3]), "r"(b0), "r"(b1))

// ======================= scratch =============================================
__device__ __align__(256) float  g_u   [M_TOK];
__device__ __align__(256) float  g_adisc[(size_t)M_TOK * DSTATE];
__device__ __align__(256) float  g_bu  [(size_t)M_TOK * DSTATE];
__device__ __align__(256) float  g_y   [(size_t)M_TOK * DSTATE];
// fp16 planes
__device__ __align__(256) __half g_xh  [(size_t)M_TOK * DIM];
__device__ __align__(256) __half g_xih [(size_t)M_TOK * DINNER];
__device__ __align__(256) __half g_resh[(size_t)M_TOK * DINNER];
__device__ __align__(256) __half g_xah [(size_t)M_TOK * DINNER];
__device__ __align__(256) __half g_yh  [(size_t)M_TOK * DINNER];
__device__ __align__(256) __half g_wih [(size_t)2*DINNER * DIM];
__device__ __align__(256) __half g_woh [(size_t)DIM * DINNER];
__device__ __align__(256) __half g_wch [2 * DSTATE * DINNER];
// scan constants
#define SCHUNK  128
#define NCHUNK  (SEQLEN / SCHUNK)   // 32

// ======================= HMMA fp16 GEMM ======================================
// Block tile 128x128, 256 threads (8 warps 4x2, warp tile 32x64),
// K-chunk 64, 3-stage cp.async pipeline, ONE __syncthreads per chunk.
// MODE 0: fp32 C (Nglob stride). MODE 1: write g_xih. MODE 2: silu -> g_resh.
#define LG_ROWB   144
#define A_OFF_B   0
#define B_OFF_B   (128 * LG_ROWB)          // 18432
#define STAGE_B   (2 * 128 * LG_ROWB)      // 36864 per stage (A+B)
#define GH_SMEM   (3 * STAGE_B)            // 110592

template<int MODE>
__global__ __launch_bounds__(256, 2)
void gemm_hmma(const __half* __restrict__ A, const __half* __restrict__ B,
               float* __restrict__ C, int Nglob, int K, int m_off)
{
    extern __shared__ char smem[];
    const uint32_t sb = smem_to_u32(smem);
    const int tid  = threadIdx.x;
    const int wid  = tid >> 5;
    const int lane = tid & 31;
    const int m0 = m_off + blockIdx.y * 128;
    const int n0 = blockIdx.x * 128;
    const int nch = K / 64;

    const int wm = (wid & 3) * 32;
    const int wn = (wid >> 2) * 64;

    float acc[2][8][4];
#pragma unroll
    for (int i = 0; i < 2; i++)
#pragma unroll
        for (int j = 0; j < 8; j++)
#pragma unroll
            for (int k = 0; k < 4; k++) acc[i][j][k] = 0.f;

    auto issue = [&](int c, int s) {
        const __half* Ag = A + (size_t)m0 * K + (size_t)c * 64;
        const __half* Bg = B + (size_t)n0 * K + (size_t)c * 64;
        const uint32_t sa  = sb + (uint32_t)(s * STAGE_B) + A_OFF_B;
        const uint32_t sbm = sb + (uint32_t)(s * STAGE_B) + B_OFF_B;
#pragma unroll
        for (int i = 0; i < 4; i++) {
            int idx = tid + i * 256;
            int row = idx >> 3, cc = idx & 7;
            CP_ASYNC16(sa  + (uint32_t)(row * LG_ROWB + cc * 16),
                       Ag + (size_t)row * K + cc * 8);
            CP_ASYNC16(sbm + (uint32_t)(row * LG_ROWB + cc * 16),
                       Bg + (size_t)row * K + cc * 8);
        }
        CP_COMMIT();
    };

    issue(0, 0);
    if (nch > 1) issue(1, 1);

    int stage = 0;
    for (int c = 0; c < nch; c++) {
        if (c + 1 < nch) { CP_WAIT1(); } else { CP_WAIT0(); }
        __syncthreads();

        const uint32_t aBase = sb + (uint32_t)(stage * STAGE_B) + A_OFF_B;
        const uint32_t bBase = sb + (uint32_t)(stage * STAGE_B) + B_OFF_B;
        const int lrow = lane & 15;
        const int lcol = (lane >> 4) * 16;
#pragma unroll
        for (int ks = 0; ks < 4; ks++) {
            uint32_t af[2][4], bfr[4][4];
#pragma unroll
            for (int mt = 0; mt < 2; mt++)
                LDSM_X4(af[mt], aBase + (uint32_t)((wm + mt*16 + lrow) * LG_ROWB + ks*32 + lcol));
#pragma unroll
            for (int ng = 0; ng < 4; ng++)
                LDSM_X4(bfr[ng], bBase + (uint32_t)((wn + ng*16 + lrow) * LG_ROWB + ks*32 + lcol));
#pragma unroll
            for (int mt = 0; mt < 2; mt++)
#pragma unroll
                for (int nt = 0; nt < 8; nt++) {
                    const int ng = nt >> 1, hi = nt & 1;
                    MMA_F16(acc[mt][nt], af[mt], bfr[ng][hi], bfr[ng][2 + hi]);
                }
        }
        // issue chunk c+2 into the stage last read at iteration c-1 (safe: all
        // warps passed this iteration's __syncthreads, so compute(c-1) is done)
        if (c + 2 < nch) issue(c + 2, (stage + 2) % 3);
        stage = (stage + 1) % 3;
    }

    const int er = lane >> 2;
    const int ec = (lane & 3) * 2;
#pragma unroll
    for (int mt = 0; mt < 2; mt++) {
        const int rbase = m0 + wm + mt * 16;
#pragma unroll
        for (int nt = 0; nt < 8; nt++) {
            const int col = n0 + wn + nt * 8 + ec;
            float v0 = acc[mt][nt][0], v1 = acc[mt][nt][1];
            float v2 = acc[mt][nt][2], v3 = acc[mt][nt][3];
            if (MODE == 0) {
                *reinterpret_cast<float2*>(C + (size_t)(rbase + er)     * Nglob + col) =
                    make_float2(v0, v1);
                *reinterpret_cast<float2*>(C + (size_t)(rbase + er + 8) * Nglob + col) =
                    make_float2(v2, v3);
            } else if (MODE == 1) {
                *reinterpret_cast<__half2*>(g_xih + (size_t)(rbase + er)     * DINNER + col) =
                    __floats2half2_rn(v0, v1);
                *reinterpret_cast<__half2*>(g_xih + (size_t)(rbase + er + 8) * DINNER + col) =
                    __floats2half2_rn(v2, v3);
            } else {
                v0 = v0 / (1.f + expf(-v0));
                v1 = v1 / (1.f + expf(-v1));
                v2 = v2 / (1.f + expf(-v2));
                v3 = v3 / (1.f + expf(-v3));
                *reinterpret_cast<__half2*>(g_resh + (size_t)(rbase + er)     * DINNER + col) =
                    __floats2half2_rn(v0, v1);
                *reinterpret_cast<__half2*>(g_resh + (size_t)(rbase + er + 8) * DINNER + col) =
                    __floats2half2_rn(v2, v3);
            }
        }
    }
}

// ============== small HMMA GEMM fused with dt/A_disc/Bu epilogue =============
// 3-stage A pipeline, one sync per chunk. B resident in smem.
#define SB_ROWB   2064
#define SB_BYTES  (32 * SB_ROWB)              // 66048
#define SA_TILE   (128 * LG_ROWB)             // 18432
#define GS_SMEM   (SB_BYTES + 3 * SA_TILE)    // 121344

__global__ __launch_bounds__(256, 1)
void gemm_small(const __half* __restrict__ A, const __half* __restrict__ B,
                const float* __restrict__ bdt, const float* __restrict__ Alog)
{
    extern __shared__ char smem[];
    const uint32_t sb = smem_to_u32(smem);
    const int tid  = threadIdx.x;
    const int wid  = tid >> 5;
    const int lane = tid & 31;
    const int m0 = blockIdx.x * 128;
    const int K = DINNER;
    const int nch = K / 64;                  // 16

    {
#pragma unroll
        for (int i = 0; i < 16; i++) {
            int idx = tid + i * 256;
            int row = idx >> 7, cc = idx & 127;
            CP_ASYNC16(sb + (uint32_t)(row * SB_ROWB + cc * 16),
                       B + (size_t)row * K + cc * 8);
        }
        CP_COMMIT();
    }

    auto issueA = [&](int c, int s) {
        const __half* Ag = A + (size_t)m0 * K + (size_t)c * 64;
        const uint32_t sa = sb + (uint32_t)(SB_BYTES + s * SA_TILE);
#pragma unroll
        for (int i = 0; i < 4; i++) {
            int idx = tid + i * 256;
            int row = idx >> 3, cc = idx & 7;
            CP_ASYNC16(sa + (uint32_t)(row * LG_ROWB + cc * 16),
                       Ag + (size_t)row * K + cc * 8);
        }
        CP_COMMIT();
    };

    const int wm = wid * 16;
    float acc[4][4];
#pragma unroll
    for (int j = 0; j < 4; j++)
#pragma unroll
        for (int k = 0; k < 4; k++) acc[j][k] = 0.f;

    issueA(0, 0);
    issueA(1, 1);
    // outstanding groups: B, A0, A1

    int stage = 0;
    for (int c = 0; c < nch; c++) {
        if (c + 1 < nch) { CP_WAIT1(); } else { CP_WAIT0(); }
        __syncthreads();

        const uint32_t aBase = sb + (uint32_t)(SB_BYTES + stage * SA_TILE);
        const int lrow = lane & 15;
        const int lcol = (lane >> 4) * 16;
#pragma unroll
        for (int ks = 0; ks < 4; ks++) {
            uint32_t af[4], bfr[2][4];
            LDSM_X4(af, aBase + (uint32_t)((wm + lrow) * LG_ROWB + ks*32 + lcol));
#pragma unroll
            for (int ng = 0; ng < 2; ng++)
                LDSM_X4(bfr[ng], sb + (uint32_t)((ng*16 + lrow) * SB_ROWB + (c*4 + ks)*32 + lcol));
#pragma unroll
            for (int nt = 0; nt < 4; nt++) {
                const int ng = nt >> 1, hi = nt & 1;
                MMA_F16(acc[nt], af, bfr[ng][hi], bfr[ng][2 + hi]);
            }
        }
        if (c + 2 < nch) issueA(c + 2, (stage + 2) % 3);
        stage = (stage + 1) % 3;
    }

    const int er = lane >> 2;
    const int ec = (lane & 3) * 2;
    const int r0 = m0 + wm + er;
    const float u0 = g_u[r0];
    const float u1 = g_u[r0 + 8];
#pragma unroll
    for (int nt = 0; nt < 2; nt++) {
#pragma unroll
        for (int j = 0; j < 2; j++) {
            const int n = nt * 8 + ec + j;
            const float A = -expf(Alog[n]);
            const float bn = bdt[n];
            {
                float raw = acc[nt][j] + bn;
                float dt  = raw > 20.f ? raw : log1pf(expf(raw));
                g_adisc[(size_t)r0 * DSTATE + n] = expf(A * dt);
                g_bu   [(size_t)r0 * DSTATE + n] = dt * acc[nt + 2][j] * u0;
            }
            {
                float raw = acc[nt][2 + j] + bn;
                float dt  = raw > 20.f ? raw : log1pf(expf(raw));
                g_adisc[(size_t)(r0 + 8) * DSTATE + n] = expf(A * dt);
                g_bu   [(size_t)(r0 + 8) * DSTATE + n] = dt * acc[nt + 2][2 + j] * u1;
            }
        }
    }
}

// ======================= prep kernels ========================================
__global__ void prep_x_kernel(const float* __restrict__ x)
{
    long i = ((long)blockIdx.x * 256 + threadIdx.x) * 4;
    float4 v = *reinterpret_cast<const float4*>(x + i);
    *reinterpret_cast<__half2*>(g_xh + i)     = __floats2half2_rn(v.x, v.y);
    *reinterpret_cast<__half2*>(g_xh + i + 2) = __floats2half2_rn(v.z, v.w);
}
__global__ void prep_w_kernel(const float* __restrict__ W_in, const float* __restrict__ W_out,
                              const float* __restrict__ Wx, const float* __restrict__ Wdt)
{
    const int b = blockIdx.x;
    if (b < 1024) {
        long i = ((long)b * 256 + threadIdx.x) * 4;
        float4 v = *reinterpret_cast<const float4*>(W_in + i);
        *reinterpret_cast<__half2*>(g_wih + i)     = __floats2half2_rn(v.x, v.y);
        *reinterpret_cast<__half2*>(g_wih + i + 2) = __floats2half2_rn(v.z, v.w);
    } else if (b < 1536) {
        long i = ((long)(b - 1024) * 256 + threadIdx.x) * 4;
        float4 v = *reinterpret_cast<const float4*>(W_out + i);
        *reinterpret_cast<__half2*>(g_woh + i)     = __floats2half2_rn(v.x, v.y);
        *reinterpret_cast<__half2*>(g_woh + i + 2) = __floats2half2_rn(v.z, v.w);
    } else {
        int i = (b - 1536) * 1024 + threadIdx.x * 4;
        int row = i >> 10;
        const float* src = (row < DSTATE) ? Wdt : Wx;
        float4 v = *reinterpret_cast<const float4*>(src + i);
        *reinterpret_cast<__half2*>(g_wch + i)     = __floats2half2_rn(v.x, v.y);
        *reinterpret_cast<__half2*>(g_wch + i + 2) = __floats2half2_rn(v.z, v.w);
    }
}

// ======================= conv: rolling window, coalesced =====================
#define CONV_T 32
__global__ __launch_bounds__(256)
void conv_silu_kernel(const float* __restrict__ cw, const float* __restrict__ cb)
{
    const int c4 = threadIdx.x;
    const int c  = c4 * 4;
    const int t0 = blockIdx.x * CONV_T;
    const int l0 = t0 & (SEQLEN - 1);

    float w[4][4];
#pragma unroll
    for (int j = 0; j < 4; j++)
        *reinterpret_cast<float4*>(w[j]) =
            *reinterpret_cast<const float4*>(cw + (size_t)(c + j) * DCONV);
    const float4 bias = *reinterpret_cast<const float4*>(cb + c);

    auto loadrow = [&](int t) -> float4 {
        const __half* xp = g_xih + (size_t)t * DINNER + c;
        float2 f0 = __half22float2(*reinterpret_cast<const __half2*>(xp));
        float2 f1 = __half22float2(*reinterpret_cast<const __half2*>(xp + 2));
        return make_float4(f0.x, f0.y, f1.x, f1.y);
    };

    float4 h0, h1, h2;
    if (l0 != 0) {
        h0 = loadrow(t0 - 3); h1 = loadrow(t0 - 2); h2 = loadrow(t0 - 1);
    } else {
        h0 = make_float4(0.f, 0.f, 0.f, 0.f); h1 = h0; h2 = h0;
    }
    float4 cur = loadrow(t0);

#pragma unroll 4
    for (int i = 0; i < CONV_T; i++) {
        float4 nxt = make_float4(0.f, 0.f, 0.f, 0.f);
        if (i + 1 < CONV_T) nxt = loadrow(t0 + i + 1);

        float a0 = bias.x, a1 = bias.y, a2 = bias.z, a3 = bias.w;
        a0 = fmaf(w[0][0], h0.x, a0); a0 = fmaf(w[0][1], h1.x, a0);
        a0 = fmaf(w[0][2], h2.x, a0); a0 = fmaf(w[0][3], cur.x, a0);
        a1 = fmaf(w[1][0], h0.y, a1); a1 = fmaf(w[1][1], h1.y, a1);
        a1 = fmaf(w[1][2], h2.y, a1); a1 = fmaf(w[1][3], cur.y, a1);
        a2 = fmaf(w[2][0], h0.z, a2); a2 = fmaf(w[2][1], h1.z, a2);
        a2 = fmaf(w[2][2], h2.z, a2); a2 = fmaf(w[2][3], cur.z, a2);
        a3 = fmaf(w[3][0], h0.w, a3); a3 = fmaf(w[3][1], h1.w, a3);
        a3 = fmaf(w[3][2], h2.w, a3); a3 = fmaf(w[3][3], cur.w, a3);

        float o0 = a0 / (1.f + expf(-a0));
        float o1 = a1 / (1.f + expf(-a1));
        float o2 = a2 / (1.f + expf(-a2));
        float o3 = a3 / (1.f + expf(-a3));

        __half* hp = g_xah + (size_t)(t0 + i) * DINNER + c;
        *reinterpret_cast<__half2*>(hp)     = __floats2half2_rn(o0, o1);
        *reinterpret_cast<__half2*>(hp + 2) = __floats2half2_rn(o2, o3);

        if (c4 < 16) {
            float s = o0 + o1 + o2 + o3;
#pragma unroll
            for (int o = 8; o; o >>= 1) s += __shfl_down_sync(0xffffu, s, o);
            if (c4 == 0) g_u[t0 + i] = s * (1.f / 64.f);
        }
        h0 = h1; h1 = h2; h2 = cur; cur = nxt;
    }
}

// ======================= fused 3-phase scan (grid=BATCH, block=512) ==========
__global__ void scan_kernel()
{
    __shared__ float sA[NCHUNK][DSTATE];
    __shared__ float sV[NCHUNK][DSTATE];
    __shared__ float sC[NCHUNK][DSTATE];
    const int b = blockIdx.x;
    const int tid = threadIdx.x;
    const int c = tid >> 4;
    const int n = tid & 15;
    const size_t base = ((size_t)b * SEQLEN + (size_t)c * SCHUNK) * DSTATE + n;

    float A = 1.f, V = 0.f;
#pragma unroll 8
    for (int i = 0; i < SCHUNK; i++) {
        float a = g_adisc[base + (size_t)i * DSTATE];
        float v = g_bu   [base + (size_t)i * DSTATE];
        V = fmaf(a, V, v);
        A *= a;
    }
    sA[c][n] = A; sV[c][n] = V;
    __syncthreads();
    if (tid < DSTATE) {
        float s = 0.f;
#pragma unroll
        for (int cc = 0; cc < NCHUNK; cc++) {
            sC[cc][tid] = s;
            s = fmaf(sA[cc][tid], s, sV[cc][tid]);
        }
    }
    __syncthreads();
    float s = sC[c][n];
#pragma unroll 8
    for (int i = 0; i < SCHUNK; i++) {
        float a = g_adisc[base + (size_t)i * DSTATE];
        float v = g_bu   [base + (size_t)i * DSTATE];
        s = fmaf(a, s, v);
        g_y[base + (size_t)i * DSTATE] = s;
    }
}

// ======================= gate + skip -> fp16 y_full ===========================
__global__ void elt_kernel(const float* __restrict__ Dp, int m_off)
{
    int idx = blockIdx.x * blockDim.x + threadIdx.x;
    int c4 = idx & (DINNER/4 - 1);
    int m  = m_off + (idx >> 8);
    int c  = c4 * 4;
    float yv  = g_y[(size_t)m * DSTATE + (c >> 6)];
    const __half* xp = g_xah + (size_t)m * DINNER + c;
    float2 x0 = __half22float2(*reinterpret_cast<const __half2*>(xp));
    float2 x1 = __half22float2(*reinterpret_cast<const __half2*>(xp + 2));
    float4 D  = *reinterpret_cast<const float4*>(Dp + c);
    const __half* rp = g_resh + (size_t)m * DINNER + c;
    float2 r0 = __half22float2(*reinterpret_cast<const __half2*>(rp));
    float2 r1 = __half22float2(*reinterpret_cast<const __half2*>(rp + 2));
    float o0 = (yv + x0.x * D.x) * r0.x;
    float o1 = (yv + x0.y * D.y) * r0.y;
    float o2 = (yv + x1.x * D.z) * r1.x;
    float o3 = (yv + x1.y * D.w) * r1.y;
    __half* row = g_yh + (size_t)m * DINNER + c;
    *reinterpret_cast<__half2*>(row)     = __floats2half2_rn(o0, o1);
    *reinterpret_cast<__half2*>(row + 2) = __floats2half2_rn(o2, o3);
}

// ======================= launch ==============================================
extern "C" void kernel_launch(void* const* d_in, const int* in_sizes, int n_in,
                              void* d_out, int out_size)
{
    const float* x      = (const float*)d_in[0];
    const float* W_in   = (const float*)d_in[1];
    const float* conv_w = (const float*)d_in[2];
    const float* conv_b = (const float*)d_in[3];
    const float* W_x    = (const float*)d_in[4];
    const float* W_dt   = (const float*)d_in[5];
    const float* b_dt   = (const float*)d_in[6];
    const float* A_log  = (const float*)d_in[7];
    const float* D_par  = (const float*)d_in[8];
    const float* W_out  = (const float*)d_in[9];
    float* out = (float*)d_out;

    __half* xh;  cudaGetSymbolAddress((void**)&xh,  g_xh);
    __half* xah; cudaGetSymbolAddress((void**)&xah, g_xah);
    __half* yh;  cudaGetSymbolAddress((void**)&yh,  g_yh);
    __half* wih; cudaGetSymbolAddress((void**)&wih, g_wih);
    __half* woh; cudaGetSymbolAddress((void**)&woh, g_woh);
    __half* wch; cudaGetSymbolAddress((void**)&wch, g_wch);

    cudaFuncSetAttribute(gemm_hmma<0>, cudaFuncAttributeMaxDynamicSharedMemorySize, GH_SMEM);
    cudaFuncSetAttribute(gemm_hmma<1>, cudaFuncAttributeMaxDynamicSharedMemorySize, GH_SMEM);
    cudaFuncSetAttribute(gemm_hmma<2>, cudaFuncAttributeMaxDynamicSharedMemorySize, GH_SMEM);
    cudaFuncSetAttribute(gemm_small,   cudaFuncAttributeMaxDynamicSharedMemorySize, GS_SMEM);

    cudaStream_t s2;
    cudaStreamCreateWithFlags(&s2, cudaStreamNonBlocking);
    cudaEvent_t ev0, evW, evA, evB, evScan, evE1;
    cudaEventCreateWithFlags(&ev0,    cudaEventDisableTiming);
    cudaEventCreateWithFlags(&evW,    cudaEventDisableTiming);
    cudaEventCreateWithFlags(&evA,    cudaEventDisableTiming);
    cudaEventCreateWithFlags(&evB,    cudaEventDisableTiming);
    cudaEventCreateWithFlags(&evScan, cudaEventDisableTiming);
    cudaEventCreateWithFlags(&evE1,   cudaEventDisableTiming);

    cudaEventRecord(ev0, 0);
    cudaStreamWaitEvent(s2, ev0, 0);
    prep_w_kernel<<<1568, 256, 0, s2>>>(W_in, W_out, W_x, W_dt);
    cudaEventRecord(evW, s2);

    prep_x_kernel<<<(M_TOK*DIM)/1024, 256>>>(x);
    cudaStreamWaitEvent(0, evW, 0);

    // GEMM1a: xi half -> g_xih
    gemm_hmma<1><<<dim3(DINNER/128, M_TOK/128), 256, GH_SMEM>>>(
        xh, wih, nullptr, 0, DIM, 0);

    // fork: GEMM1b res half on s2 (silu -> g_resh)
    cudaEventRecord(evA, 0);
    cudaStreamWaitEvent(s2, evA, 0);
    gemm_hmma<2><<<dim3(DINNER/128, M_TOK/128), 256, GH_SMEM, s2>>>(
        xh, wih + (size_t)DINNER * DIM, nullptr, 0, DIM, 0);
    cudaEventRecord(evB, s2);

    // dependent chain on main (overlaps GEMM1b)
    conv_silu_kernel<<<M_TOK/CONV_T, 256>>>(conv_w, conv_b);
    gemm_small<<<M_TOK/128, 256, GS_SMEM>>>(xah, wch, b_dt, A_log);
    scan_kernel<<<BATCH, 512>>>();
    cudaEventRecord(evScan, 0);

    // tail split: elt_h0 on main; elt_h1 on s2
    cudaStreamWaitEvent(0, evB, 0);
    elt_kernel<<<(M_TOK/2)*(DINNER/4)/256, 256>>>(D_par, 0);
    cudaStreamWaitEvent(s2, evScan, 0);
    elt_kernel<<<(M_TOK/2)*(DINNER/4)/256, 256, 0, s2>>>(D_par, M_TOK/2);
    cudaEventRecord(evE1, s2);

    // GEMM2 halves: h0 overlaps elt_h1
    gemm_hmma<0><<<dim3(DIM/128, M_TOK/256), 256, GH_SMEM>>>(
        yh, woh, out, DIM, DINNER, 0);
    cudaStreamWaitEvent(0, evE1, 0);
    gemm_hmma<0><<<dim3(DIM/128, M_TOK/256), 256, GH_SMEM>>>(
        yh, woh, out, DIM, DINNER, M_TOK/2);
}